// round 9
// baseline (speedup 1.0000x reference)
#include <cuda_runtime.h>
#include <cuda_bf16.h>
#include <cstdint>

// Problem constants
#define Bn   64
#define Cc   768
#define HW   676          // 26*26
#define Mm   32
#define NCLS 200
#define MC   (Mm*Cc)      // 24576
#define OFF_P   0
#define OFF_FM  (Bn*NCLS)                  // 12800
#define OFF_ATT (OFF_FM + Bn*MC)           // 12800 + 1572864

// Scratch (no allocation allowed -> device globals).
// NEVER pass these as host-side kernel arguments — device-code use only.
__device__ float g_fmraw[Bn * MC];     // pooled bilinear features before sqrt
__device__ float g_scale[Bn];          // 1/max(||f||,eps)
__device__ float g_scale100[Bn];       // 100/max(||f||,eps)

// ===========================================================================
// Baseline-ISA tensor helpers (ldmatrix + mma.sync assemble for plain sm_103;
// tcgen05 does NOT — harness assembles a non-'a' target).
// ===========================================================================
__device__ __forceinline__ uint32_t smem_u32(const void* p) {
    uint32_t r;
    asm("{ .reg .u64 t; cvta.to.shared.u64 t, %1; cvt.u32.u64 %0, t; }"
        : "=r"(r) : "l"(p));
    return r;
}
#define SWZ128(o)  ((o) ^ (((o) >> 3) & 0x70))

__device__ __forceinline__ void ldsm_x4(uint32_t addr, uint32_t r[4]) {
    asm volatile("ldmatrix.sync.aligned.m8n8.x4.shared.b16 {%0,%1,%2,%3}, [%4];"
                 : "=r"(r[0]), "=r"(r[1]), "=r"(r[2]), "=r"(r[3]) : "r"(addr));
}
__device__ __forceinline__ void mma_bf16(float* c, const uint32_t a[4],
                                         uint32_t b0, uint32_t b1) {
    asm volatile(
        "mma.sync.aligned.m16n8k16.row.col.f32.bf16.bf16.f32 "
        "{%0,%1,%2,%3}, {%4,%5,%6,%7}, {%8,%9}, {%0,%1,%2,%3};"
        : "+f"(c[0]), "+f"(c[1]), "+f"(c[2]), "+f"(c[3])
        : "r"(a[0]), "r"(a[1]), "r"(a[2]), "r"(a[3]), "r"(b0), "r"(b1));
}

// ---------------------------------------------------------------------------
// Kernel A (SIMT, passing since R6; split over b for profiling slot):
// att_m[b,m,hw] = relu( sum_c fm[b,c,hw] * att_w[m,c] + att_b[m] ), m<32
// ---------------------------------------------------------------------------
__global__ __launch_bounds__(128) void k_att(
    const float* __restrict__ fmap, const float* __restrict__ attw,
    const float* __restrict__ attb, float* __restrict__ out_att, int b0)
{
    __shared__ __align__(16) float Ws[64 * 32];
    const int b  = b0 + blockIdx.y;
    const int hw = blockIdx.x * 128 + threadIdx.x;
    const int hwc = hw < HW ? hw : (HW - 1);

    float acc[32];
#pragma unroll
    for (int m = 0; m < 32; ++m) acc[m] = 0.f;

    for (int c0 = 0; c0 < Cc; c0 += 64) {
        __syncthreads();
#pragma unroll
        for (int i = 0; i < 16; ++i) {
            int e  = threadIdx.x + i * 128;
            int cp = e & 63;
            int m  = e >> 6;
            float val = attw[m * Cc + c0 + cp];
            Ws[cp * 32 + (((m >> 2) ^ (cp & 7)) << 2) + (m & 3)] = val;
        }
        __syncthreads();

        const float* fp = fmap + ((size_t)b * Cc + c0) * HW + hwc;
        for (int cb = 0; cb < 4; ++cb) {
#pragma unroll
            for (int u = 0; u < 16; ++u) {
                const int cc = cb * 16 + u;
                float v = fp[cc * HW];
#pragma unroll
                for (int j = 0; j < 8; ++j) {
                    const int jm = j ^ (u & 7);
                    float4 w4 = *(const float4*)&Ws[cc * 32 + j * 4];
                    acc[4 * jm + 0] += w4.x * v;
                    acc[4 * jm + 1] += w4.y * v;
                    acc[4 * jm + 2] += w4.z * v;
                    acc[4 * jm + 3] += w4.w * v;
                }
            }
        }
    }

    if (hw < HW) {
        float* op = out_att + ((size_t)b * Mm) * HW + hw;
#pragma unroll
        for (int m = 0; m < 32; ++m) {
            float a = acc[m] + __ldg(&attb[m]);
            op[m * HW] = fmaxf(a, 0.f);
        }
    }
}

// ---------------------------------------------------------------------------
// Kernel B (mma.sync): g_fmraw[b,m,c] = (1/676) sum_hw att[b,m,hw] fm[b,c,hw]
// Per CTA (c-tile of 128, batch b): D[128c x 32m] = A[128c x K] @ B[32m x K]^T
// K = hw in 11 chunks of 64 (last zero-padded).
// bf16 hi/lo split, 3 mma products, fp32 register accumulators.
// Both A and B are K-major in SMEM ([row][k]) -> NON-trans ldmatrix for both.
// (R8 bug: .trans on B swapped n<->k in the fragment.)
// ---------------------------------------------------------------------------
#define CH       64
#define NCHUNK   11
#define A_HI_OFF 0
#define A_LO_OFF 16384
#define B_HI_OFF 32768
#define B_LO_OFF 36864
#define POOL_SMEM_DYN (40 * 1024 + 1024)

__device__ __forceinline__ void split_pack(float x, float y,
                                           uint32_t& hi, uint32_t& lo) {
    __nv_bfloat16 hx = __float2bfloat16_rn(x);
    __nv_bfloat16 hy = __float2bfloat16_rn(y);
    __nv_bfloat16 lx = __float2bfloat16_rn(x - __bfloat162float(hx));
    __nv_bfloat16 ly = __float2bfloat16_rn(y - __bfloat162float(hy));
    hi = ((uint32_t)__bfloat16_as_ushort(hy) << 16) | __bfloat16_as_ushort(hx);
    lo = ((uint32_t)__bfloat16_as_ushort(ly) << 16) | __bfloat16_as_ushort(lx);
}

__global__ __launch_bounds__(256) void k_pool_mma(
    const float* __restrict__ fmap, const float* __restrict__ att)
{
    extern __shared__ char dyn_smem[];

    const int b  = blockIdx.y;
    const int c0 = blockIdx.x * 128;
    const int t  = threadIdx.x;
    const int w  = t >> 5, lane = t & 31;
    const int rw = w * 16;                  // warp's c-row base in tile

    // 1024-align tile base so SWZ128 sees tile-relative offsets
    uint32_t raw = smem_u32(dyn_smem);
    uint32_t abase = (raw + 1023u) & ~1023u;
    char* sbuf = dyn_smem + (abase - raw);

    const float* Aruns = fmap + (size_t)(b * Cc + c0) * HW;
    const float* Bruns = att  + (size_t)b * Mm * HW;

    float acc[4][4];                        // 4 n-tiles of 8 x (d0..d3)
#pragma unroll
    for (int p = 0; p < 4; ++p)
#pragma unroll
        for (int j = 0; j < 4; ++j) acc[p][j] = 0.f;

    // Per-lane ldmatrix bases (lane-constant across chunks).
    // x4 non-trans lane->matrix map: lanes 0-7 mat0, 8-15 mat1, 16-23 mat2,
    // 24-31 mat3. A: mat0 rows0-7/k0-7, mat1 rows8-15/k0-7, mat2 rows0-7/k8-15,
    // mat3 rows8-15/k8-15 (matches a0..a3). B: mat0 n0-7/k0-7, mat1 n0-7/k8-15
    // (b0,b1 of first 8x8 n-tile), mat2/3 same for n8-15.
    const int r8   = lane & 7;
    const int aRow = rw + ((lane >> 3) & 1) * 8 + r8;
    const int aColM = ((lane >> 4) & 1) * 16;
    const int bRow0 = ((lane >> 4) & 1) * 8 + r8;
    const int bColM = ((lane >> 3) & 1) * 16;

    for (int chunk = 0; chunk < NCHUNK; ++chunk) {
        const int hw0 = chunk * CH;
        __syncthreads();                    // previous chunk's mma consumed smem
        // ---- stage A tile (128 x 64 fp32 -> hi/lo bf16, SW128) ----
#pragma unroll
        for (int i = 0; i < 8; ++i) {
            int q = t + i * 256;            // 0..2047 float4 quads
            int row = q >> 4, qc = q & 15;
            float4 v = make_float4(0.f, 0.f, 0.f, 0.f);
            if (hw0 + qc * 4 + 3 < HW)
                v = *(const float4*)(Aruns + (size_t)row * HW + hw0 + qc * 4);
            uint32_t h01, l01, h23, l23;
            split_pack(v.x, v.y, h01, l01);
            split_pack(v.z, v.w, h23, l23);
            uint32_t off = SWZ128((uint32_t)(row * 128 + qc * 8));
            *(uint32_t*)(sbuf + A_HI_OFF + off)     = h01;
            *(uint32_t*)(sbuf + A_HI_OFF + off + 4) = h23;
            *(uint32_t*)(sbuf + A_LO_OFF + off)     = l01;
            *(uint32_t*)(sbuf + A_LO_OFF + off + 4) = l23;
        }
        // ---- stage B tile (32 x 64) ----
#pragma unroll
        for (int i = 0; i < 2; ++i) {
            int q = t + i * 256;            // 0..511
            int row = q >> 4, qc = q & 15;
            float4 v = make_float4(0.f, 0.f, 0.f, 0.f);
            if (hw0 + qc * 4 + 3 < HW)
                v = *(const float4*)(Bruns + (size_t)row * HW + hw0 + qc * 4);
            uint32_t h01, l01, h23, l23;
            split_pack(v.x, v.y, h01, l01);
            split_pack(v.z, v.w, h23, l23);
            uint32_t off = SWZ128((uint32_t)(row * 128 + qc * 8));
            *(uint32_t*)(sbuf + B_HI_OFF + off)     = h01;
            *(uint32_t*)(sbuf + B_HI_OFF + off + 4) = h23;
            *(uint32_t*)(sbuf + B_LO_OFF + off)     = l01;
            *(uint32_t*)(sbuf + B_LO_OFF + off + 4) = l23;
        }
        __syncthreads();

        // ---- 4 k-steps of 16 over this chunk ----
#pragma unroll
        for (int ks = 0; ks < 4; ++ks) {
            const uint32_t aOff = SWZ128((uint32_t)(aRow * 128 + ks * 32 + aColM));
            uint32_t ah[4], al[4];
            ldsm_x4(abase + A_HI_OFF + aOff, ah);
            ldsm_x4(abase + A_LO_OFF + aOff, al);
#pragma unroll
            for (int pp = 0; pp < 2; ++pp) {    // n-tile pairs {0,1},{2,3}
                const uint32_t bOff =
                    SWZ128((uint32_t)((pp * 16 + bRow0) * 128 + ks * 32 + bColM));
                uint32_t bh[4], bl[4];
                ldsm_x4(abase + B_HI_OFF + bOff, bh);   // NON-trans (K-major B)
                ldsm_x4(abase + B_LO_OFF + bOff, bl);
                // tile 2pp  : regs {0,1};  tile 2pp+1: regs {2,3}
                mma_bf16(acc[2 * pp],     ah, bh[0], bh[1]);
                mma_bf16(acc[2 * pp],     ah, bl[0], bl[1]);
                mma_bf16(acc[2 * pp],     al, bh[0], bh[1]);
                mma_bf16(acc[2 * pp + 1], ah, bh[2], bh[3]);
                mma_bf16(acc[2 * pp + 1], ah, bl[2], bl[3]);
                mma_bf16(acc[2 * pp + 1], al, bh[2], bh[3]);
            }
        }
    }

    // ---- epilogue: D[c_local, n=m] / 676 -> g_fmraw[b, m, c0+c_local] ----
    const float inv = 1.f / (float)HW;
    const int crow = c0 + rw + (lane >> 2);
#pragma unroll
    for (int p = 0; p < 4; ++p) {
        const int n = p * 8 + (lane & 3) * 2;
        g_fmraw[((size_t)b * Mm + n)     * Cc + crow]     = acc[p][0] * inv;
        g_fmraw[((size_t)b * Mm + n + 1) * Cc + crow]     = acc[p][1] * inv;
        g_fmraw[((size_t)b * Mm + n)     * Cc + crow + 8] = acc[p][2] * inv;
        g_fmraw[((size_t)b * Mm + n + 1) * Cc + crow + 8] = acc[p][3] * inv;
    }
}

// ---------------------------------------------------------------------------
// Kernel C: f = sign(x)*sqrt(|x|+eps); unnormalized f -> out_fm;
// per-batch sumsq -> g_scale / g_scale100.
// ---------------------------------------------------------------------------
__global__ __launch_bounds__(1024) void k_ssqrt(float* __restrict__ out_fm)
{
    const int b = blockIdx.x;
    float ss = 0.f;
    for (int e = threadIdx.x; e < MC; e += 1024) {
        float x = g_fmraw[b * MC + e];
        float f = (x == 0.f) ? 0.f : copysignf(sqrtf(fabsf(x) + 1e-12f), x);
        out_fm[b * MC + e] = f;
        ss += f * f;
    }
    __shared__ float red[32];
#pragma unroll
    for (int o = 16; o; o >>= 1) ss += __shfl_xor_sync(0xffffffffu, ss, o);
    if ((threadIdx.x & 31) == 0) red[threadIdx.x >> 5] = ss;
    __syncthreads();
    if (threadIdx.x < 32) {
        ss = red[threadIdx.x];
#pragma unroll
        for (int o = 16; o; o >>= 1) ss += __shfl_xor_sync(0xffffffffu, ss, o);
        if (threadIdx.x == 0) {
            float nrm = sqrtf(ss);
            float s = 1.f / fmaxf(nrm, 1e-12f);
            g_scale[b] = s;
            g_scale100[b] = 100.f * s;
        }
    }
}

// p init with bias
__global__ __launch_bounds__(256) void k_p0(const float* __restrict__ fcb,
                                            float* __restrict__ out_p)
{
    int i = blockIdx.x * 256 + threadIdx.x;
    if (i < Bn * NCLS) out_p[i] = __ldg(&fcb[i % NCLS]);
}

// ---------------------------------------------------------------------------
// Kernel D: p[b,n] += sum_k f_unnorm[b,k]*(100/nrm_b) * fc_w[n,k]   (split-k)
// ---------------------------------------------------------------------------
__global__ __launch_bounds__(256) void k_fc(
    const float* __restrict__ fmn, const float* __restrict__ fcw,
    float* __restrict__ out_p)
{
    __shared__ float sfm[64 * 33];
    __shared__ float sw[16 * 32];
    const int k0 = blockIdx.x * 1024;
    const int n0 = blockIdx.y * 16;
    const int t  = threadIdx.x;
    const int tb = t & 63, tg = t >> 6;

    float s100[8];
#pragma unroll
    for (int i = 0; i < 8; ++i) s100[i] = g_scale100[(t + i * 256) >> 5];

    float acc0 = 0.f, acc1 = 0.f, acc2 = 0.f, acc3 = 0.f;

    for (int kb = 0; kb < 1024; kb += 32) {
        __syncthreads();
#pragma unroll
        for (int i = 0; i < 8; ++i) {
            int e = t + i * 256;
            int bb = e >> 5, kk = e & 31;
            sfm[bb * 33 + kk] = fmn[bb * MC + k0 + kb + kk] * s100[i];
        }
#pragma unroll
        for (int i = 0; i < 2; ++i) {
            int e = t + i * 256;
            int nn = e >> 5, kk = e & 31;
            int n = n0 + nn;
            sw[nn * 32 + kk] = (n < NCLS) ? fcw[(size_t)n * MC + k0 + kb + kk] : 0.f;
        }
        __syncthreads();
#pragma unroll
        for (int kk = 0; kk < 32; ++kk) {
            float v = sfm[tb * 33 + kk];
            acc0 += v * sw[(tg * 4 + 0) * 32 + kk];
            acc1 += v * sw[(tg * 4 + 1) * 32 + kk];
            acc2 += v * sw[(tg * 4 + 2) * 32 + kk];
            acc3 += v * sw[(tg * 4 + 3) * 32 + kk];
        }
    }
    int n = n0 + tg * 4;
    if (n + 0 < NCLS) atomicAdd(&out_p[tb * NCLS + n + 0], acc0);
    if (n + 1 < NCLS) atomicAdd(&out_p[tb * NCLS + n + 1], acc1);
    if (n + 2 < NCLS) atomicAdd(&out_p[tb * NCLS + n + 2], acc2);
    if (n + 3 < NCLS) atomicAdd(&out_p[tb * NCLS + n + 3], acc3);
}

// normalize fm in place (after k_fc consumed unnormalized values)
__global__ __launch_bounds__(256) void k_norm(float* __restrict__ out_fm)
{
    int i = blockIdx.x * 256 + threadIdx.x;
    if (i < Bn * MC) out_fm[i] *= g_scale[i / MC];
}

// ---------------------------------------------------------------------------
extern "C" void kernel_launch(void* const* d_in, const int* in_sizes, int n_in,
                              void* d_out, int out_size)
{
    const float* fmap = (const float*)d_in[0];
    const float* attw = (const float*)d_in[1];
    const float* attb = (const float*)d_in[2];
    const float* fcw  = (const float*)d_in[3];
    const float* fcb  = (const float*)d_in[4];
    float* out     = (float*)d_out;
    float* out_p   = out + OFF_P;
    float* out_fm  = out + OFF_FM;
    float* out_att = out + OFF_ATT;
    (void)in_sizes; (void)n_in; (void)out_size;

    // Launch order keeps the ncu capture slot (launch index 3) on a k_att part.
    k_p0  <<<(Bn * NCLS + 255) / 256, 256>>>(fcb, out_p);
    k_att <<<dim3(6, 22), 128>>>(fmap, attw, attb, out_att, 0);
    k_att <<<dim3(6, 21), 128>>>(fmap, attw, attb, out_att, 22);
    k_att <<<dim3(6, 21), 128>>>(fmap, attw, attb, out_att, 43);
    k_pool_mma<<<dim3(6, 64), 256, POOL_SMEM_DYN>>>(fmap, out_att);
    k_ssqrt<<<Bn, 1024>>>(out_fm);
    k_fc  <<<dim3(24, 13), 256>>>(out_fm, fcw, out_p);
    k_norm<<<(Bn * MC + 255) / 256, 256>>>(out_fm);
}

// round 10
// speedup vs baseline: 2.5470x; 2.5470x over previous
#include <cuda_runtime.h>
#include <cuda_bf16.h>
#include <cstdint>

// Problem constants
#define Bn   64
#define Cc   768
#define HW   676          // 26*26
#define Mm   32
#define NCLS 200
#define MC   (Mm*Cc)      // 24576
#define OFF_P   0
#define OFF_FM  (Bn*NCLS)                  // 12800
#define OFF_ATT (OFF_FM + Bn*MC)           // 12800 + 1572864

// Scratch (no allocation allowed -> device globals).
// NEVER pass these as host-side kernel arguments — device-code use only.
__device__ float g_fmraw[Bn * MC];     // pooled bilinear features before sqrt
__device__ float g_scale[Bn];          // 1/max(||f||,eps)
__device__ float g_scale100[Bn];       // 100/max(||f||,eps)

// ===========================================================================
// Baseline-ISA tensor helpers (ldmatrix + mma.sync assemble for plain sm_103;
// tcgen05 does NOT — harness assembles a non-'a' target).
// ===========================================================================
__device__ __forceinline__ uint32_t smem_u32(const void* p) {
    uint32_t r;
    asm("{ .reg .u64 t; cvta.to.shared.u64 t, %1; cvt.u32.u64 %0, t; }"
        : "=r"(r) : "l"(p));
    return r;
}
#define SWZ128(o)  ((o) ^ (((o) >> 3) & 0x70))

__device__ __forceinline__ void ldsm_x4(uint32_t addr, uint32_t r[4]) {
    asm volatile("ldmatrix.sync.aligned.m8n8.x4.shared.b16 {%0,%1,%2,%3}, [%4];"
                 : "=r"(r[0]), "=r"(r[1]), "=r"(r[2]), "=r"(r[3]) : "r"(addr));
}
__device__ __forceinline__ void ldsm_x4_t(uint32_t addr, uint32_t r[4]) {
    asm volatile("ldmatrix.sync.aligned.m8n8.x4.trans.shared.b16 {%0,%1,%2,%3}, [%4];"
                 : "=r"(r[0]), "=r"(r[1]), "=r"(r[2]), "=r"(r[3]) : "r"(addr));
}
__device__ __forceinline__ void mma_bf16(float* c, const uint32_t a[4],
                                         uint32_t b0, uint32_t b1) {
    asm volatile(
        "mma.sync.aligned.m16n8k16.row.col.f32.bf16.bf16.f32 "
        "{%0,%1,%2,%3}, {%4,%5,%6,%7}, {%8,%9}, {%0,%1,%2,%3};"
        : "+f"(c[0]), "+f"(c[1]), "+f"(c[2]), "+f"(c[3])
        : "r"(a[0]), "r"(a[1]), "r"(a[2]), "r"(a[3]), "r"(b0), "r"(b1));
}

__device__ __forceinline__ void split_pack(float x, float y,
                                           uint32_t& hi, uint32_t& lo) {
    __nv_bfloat16 hx = __float2bfloat16_rn(x);
    __nv_bfloat16 hy = __float2bfloat16_rn(y);
    __nv_bfloat16 lx = __float2bfloat16_rn(x - __bfloat162float(hx));
    __nv_bfloat16 ly = __float2bfloat16_rn(y - __bfloat162float(hy));
    hi = ((uint32_t)__bfloat16_as_ushort(hy) << 16) | __bfloat16_as_ushort(hx);
    lo = ((uint32_t)__bfloat16_as_ushort(ly) << 16) | __bfloat16_as_ushort(lx);
}

// ---------------------------------------------------------------------------
// Kernel A (mma.sync): att[b,m,hw] = relu( sum_c X[b,c,hw]*W[m,c] + bias[m] )
// Per CTA (hw-tile of 128, batch b): D[32m x 128hw] = W[32 x K] @ X[K x 128],
// K = c in 12 chunks of 64.
// A = W: [m][k] K-major rows, SW128 -> NON-trans ldmatrix.
// B = X: staged [c][hw] = [k][n] MN-major, pitch 136 bf16 (272B = 17 granules,
//        row stride 1 granule-bank mod 8 -> conflict-free) -> TRANS ldmatrix
//        (lane l gets X[k=2(l&3)][n=l>>2]: the col-major B fragment).
// bf16 hi/lo split, 3 products, fp32 accum. Warp w owns hw cols [16w,16w+16).
// ---------------------------------------------------------------------------
#define KCH      64
#define NKCH     12
#define PXB      272                    // X row pitch bytes (136 bf16)
#define X_HI_OFF 0                      // 64*272 = 17408
#define X_LO_OFF 17408
#define W_HI_OFF 34816                  // 34*1024, 1024-aligned for SW128
#define W_LO_OFF 38912
#define ATT_SMEM_DYN (43008 + 1024)

__global__ __launch_bounds__(256) void k_att_mma(
    const float* __restrict__ fmap, const float* __restrict__ attw,
    const float* __restrict__ attb, float* __restrict__ out_att)
{
    extern __shared__ char dyn_smem[];
    const int b   = blockIdx.y;
    const int hwt = blockIdx.x * 128;
    const int t   = threadIdx.x;
    const int w   = t >> 5, lane = t & 31;

    uint32_t raw = smem_u32(dyn_smem);
    uint32_t abase = (raw + 1023u) & ~1023u;
    char* sbuf = dyn_smem + (abase - raw);

    const float* X = fmap + (size_t)b * Cc * HW;

    float acc[2][2][4];                 // [m-tile][n-tile][4]
#pragma unroll
    for (int mt = 0; mt < 2; ++mt)
#pragma unroll
        for (int nt = 0; nt < 2; ++nt)
#pragma unroll
            for (int j = 0; j < 4; ++j) acc[mt][nt][j] = 0.f;

    // lane-constant ldmatrix bases
    const int r8 = lane & 7;
    const int aRowIn = ((lane >> 3) & 1) * 8 + r8;      // + mt*16
    const int aColB  = ((lane >> 4) & 1) * 16;          // byte offset (k-half)
    const int bKrow  = lane & 15;                       // + ks*16
    const int bNcol  = w * 16 + ((lane >> 4) & 1) * 8;  // hw col base

    for (int ch = 0; ch < NKCH; ++ch) {
        const int c0 = ch * KCH;
        __syncthreads();                // prev chunk's mma consumed smem
        // ---- stage X tile: rows c0..c0+63, cols hwt..hwt+127 ----
#pragma unroll
        for (int i = 0; i < 8; ++i) {
            int q = t + i * 256;        // 0..2047 quads (64 rows x 32 quads)
            int row = q >> 5, qc = q & 31;
            int hw = hwt + qc * 4;
            float4 v = make_float4(0.f, 0.f, 0.f, 0.f);
            if (hw < HW)                // HW%4==0 -> full quad in range
                v = *(const float4*)(X + (size_t)(c0 + row) * HW + hw);
            uint32_t h01, l01, h23, l23;
            split_pack(v.x, v.y, h01, l01);
            split_pack(v.z, v.w, h23, l23);
            uint32_t off = (uint32_t)(row * PXB + qc * 8);
            *(uint32_t*)(sbuf + X_HI_OFF + off)     = h01;
            *(uint32_t*)(sbuf + X_HI_OFF + off + 4) = h23;
            *(uint32_t*)(sbuf + X_LO_OFF + off)     = l01;
            *(uint32_t*)(sbuf + X_LO_OFF + off + 4) = l23;
        }
        // ---- stage W tile: rows m0..31, cols c0..c0+63 (SW128) ----
#pragma unroll
        for (int i = 0; i < 2; ++i) {
            int q = t + i * 256;        // 0..511 (32 rows x 16 quads)
            int row = q >> 4, qc = q & 15;
            float4 v = *(const float4*)(attw + (size_t)row * Cc + c0 + qc * 4);
            uint32_t h01, l01, h23, l23;
            split_pack(v.x, v.y, h01, l01);
            split_pack(v.z, v.w, h23, l23);
            uint32_t off = SWZ128((uint32_t)(row * 128 + qc * 8));
            *(uint32_t*)(sbuf + W_HI_OFF + off)     = h01;
            *(uint32_t*)(sbuf + W_HI_OFF + off + 4) = h23;
            *(uint32_t*)(sbuf + W_LO_OFF + off)     = l01;
            *(uint32_t*)(sbuf + W_LO_OFF + off + 4) = l23;
        }
        __syncthreads();

        // ---- 4 k-steps of 16 ----
#pragma unroll
        for (int ks = 0; ks < 4; ++ks) {
            uint32_t ah[2][4], al[2][4];
#pragma unroll
            for (int mt = 0; mt < 2; ++mt) {
                uint32_t aOff = SWZ128((uint32_t)((mt * 16 + aRowIn) * 128 +
                                                  ks * 32 + aColB));
                ldsm_x4(abase + W_HI_OFF + aOff, ah[mt]);
                ldsm_x4(abase + W_LO_OFF + aOff, al[mt]);
            }
            uint32_t bOff = (uint32_t)((ks * 16 + bKrow) * PXB + bNcol * 2);
            uint32_t bh[4], bl[4];
            ldsm_x4_t(abase + X_HI_OFF + bOff, bh);
            ldsm_x4_t(abase + X_LO_OFF + bOff, bl);
#pragma unroll
            for (int mt = 0; mt < 2; ++mt)
#pragma unroll
                for (int nt = 0; nt < 2; ++nt) {
                    mma_bf16(acc[mt][nt], ah[mt], bh[2 * nt], bh[2 * nt + 1]);
                    mma_bf16(acc[mt][nt], ah[mt], bl[2 * nt], bl[2 * nt + 1]);
                    mma_bf16(acc[mt][nt], al[mt], bh[2 * nt], bh[2 * nt + 1]);
                }
        }
    }

    // ---- epilogue: relu(acc + bias) -> out_att[b][m][hw] ----
    float* ob = out_att + (size_t)b * Mm * HW;
#pragma unroll
    for (int mt = 0; mt < 2; ++mt) {
        const int m  = mt * 16 + (lane >> 2);
        const float bs0 = __ldg(&attb[m]);
        const float bs8 = __ldg(&attb[m + 8]);
#pragma unroll
        for (int nt = 0; nt < 2; ++nt) {
            int hwc = hwt + w * 16 + nt * 8 + 2 * (lane & 3);
            if (hwc + 1 < HW) {
                ob[(size_t)m * HW + hwc]           = fmaxf(acc[mt][nt][0] + bs0, 0.f);
                ob[(size_t)m * HW + hwc + 1]       = fmaxf(acc[mt][nt][1] + bs0, 0.f);
                ob[(size_t)(m + 8) * HW + hwc]     = fmaxf(acc[mt][nt][2] + bs8, 0.f);
                ob[(size_t)(m + 8) * HW + hwc + 1] = fmaxf(acc[mt][nt][3] + bs8, 0.f);
            }
        }
    }
}

// ---------------------------------------------------------------------------
// Kernel B (mma.sync, passing R9): g_fmraw[b,m,c] = (1/676) sum_hw att*fm
// ---------------------------------------------------------------------------
#define CH       64
#define NCHUNK   11
#define A_HI_OFF 0
#define A_LO_OFF 16384
#define B_HI_OFF 32768
#define B_LO_OFF 36864
#define POOL_SMEM_DYN (40 * 1024 + 1024)

__global__ __launch_bounds__(256) void k_pool_mma(
    const float* __restrict__ fmap, const float* __restrict__ att)
{
    extern __shared__ char dyn_smem[];

    const int b  = blockIdx.y;
    const int c0 = blockIdx.x * 128;
    const int t  = threadIdx.x;
    const int w  = t >> 5, lane = t & 31;
    const int rw = w * 16;

    uint32_t raw = smem_u32(dyn_smem);
    uint32_t abase = (raw + 1023u) & ~1023u;
    char* sbuf = dyn_smem + (abase - raw);

    const float* Aruns = fmap + (size_t)(b * Cc + c0) * HW;
    const float* Bruns = att  + (size_t)b * Mm * HW;

    float acc[4][4];
#pragma unroll
    for (int p = 0; p < 4; ++p)
#pragma unroll
        for (int j = 0; j < 4; ++j) acc[p][j] = 0.f;

    const int r8   = lane & 7;
    const int aRow = rw + ((lane >> 3) & 1) * 8 + r8;
    const int aColM = ((lane >> 4) & 1) * 16;
    const int bRow0 = ((lane >> 4) & 1) * 8 + r8;
    const int bColM = ((lane >> 3) & 1) * 16;

    for (int chunk = 0; chunk < NCHUNK; ++chunk) {
        const int hw0 = chunk * CH;
        __syncthreads();
#pragma unroll
        for (int i = 0; i < 8; ++i) {
            int q = t + i * 256;
            int row = q >> 4, qc = q & 15;
            float4 v = make_float4(0.f, 0.f, 0.f, 0.f);
            if (hw0 + qc * 4 + 3 < HW)
                v = *(const float4*)(Aruns + (size_t)row * HW + hw0 + qc * 4);
            uint32_t h01, l01, h23, l23;
            split_pack(v.x, v.y, h01, l01);
            split_pack(v.z, v.w, h23, l23);
            uint32_t off = SWZ128((uint32_t)(row * 128 + qc * 8));
            *(uint32_t*)(sbuf + A_HI_OFF + off)     = h01;
            *(uint32_t*)(sbuf + A_HI_OFF + off + 4) = h23;
            *(uint32_t*)(sbuf + A_LO_OFF + off)     = l01;
            *(uint32_t*)(sbuf + A_LO_OFF + off + 4) = l23;
        }
#pragma unroll
        for (int i = 0; i < 2; ++i) {
            int q = t + i * 256;
            int row = q >> 4, qc = q & 15;
            float4 v = make_float4(0.f, 0.f, 0.f, 0.f);
            if (hw0 + qc * 4 + 3 < HW)
                v = *(const float4*)(Bruns + (size_t)row * HW + hw0 + qc * 4);
            uint32_t h01, l01, h23, l23;
            split_pack(v.x, v.y, h01, l01);
            split_pack(v.z, v.w, h23, l23);
            uint32_t off = SWZ128((uint32_t)(row * 128 + qc * 8));
            *(uint32_t*)(sbuf + B_HI_OFF + off)     = h01;
            *(uint32_t*)(sbuf + B_HI_OFF + off + 4) = h23;
            *(uint32_t*)(sbuf + B_LO_OFF + off)     = l01;
            *(uint32_t*)(sbuf + B_LO_OFF + off + 4) = l23;
        }
        __syncthreads();

#pragma unroll
        for (int ks = 0; ks < 4; ++ks) {
            const uint32_t aOff = SWZ128((uint32_t)(aRow * 128 + ks * 32 + aColM));
            uint32_t ah[4], al[4];
            ldsm_x4(abase + A_HI_OFF + aOff, ah);
            ldsm_x4(abase + A_LO_OFF + aOff, al);
#pragma unroll
            for (int pp = 0; pp < 2; ++pp) {
                const uint32_t bOff =
                    SWZ128((uint32_t)((pp * 16 + bRow0) * 128 + ks * 32 + bColM));
                uint32_t bh[4], bl[4];
                ldsm_x4(abase + B_HI_OFF + bOff, bh);   // NON-trans (K-major B)
                ldsm_x4(abase + B_LO_OFF + bOff, bl);
                mma_bf16(acc[2 * pp],     ah, bh[0], bh[1]);
                mma_bf16(acc[2 * pp],     ah, bl[0], bl[1]);
                mma_bf16(acc[2 * pp],     al, bh[0], bh[1]);
                mma_bf16(acc[2 * pp + 1], ah, bh[2], bh[3]);
                mma_bf16(acc[2 * pp + 1], ah, bl[2], bl[3]);
                mma_bf16(acc[2 * pp + 1], al, bh[2], bh[3]);
            }
        }
    }

    const float inv = 1.f / (float)HW;
    const int crow = c0 + rw + (lane >> 2);
#pragma unroll
    for (int p = 0; p < 4; ++p) {
        const int n = p * 8 + (lane & 3) * 2;
        g_fmraw[((size_t)b * Mm + n)     * Cc + crow]     = acc[p][0] * inv;
        g_fmraw[((size_t)b * Mm + n + 1) * Cc + crow]     = acc[p][1] * inv;
        g_fmraw[((size_t)b * Mm + n)     * Cc + crow + 8] = acc[p][2] * inv;
        g_fmraw[((size_t)b * Mm + n + 1) * Cc + crow + 8] = acc[p][3] * inv;
    }
}

// ---------------------------------------------------------------------------
// Kernel C: f = sign(x)*sqrt(|x|+eps); unnormalized f -> out_fm;
// per-batch sumsq -> g_scale / g_scale100.
// ---------------------------------------------------------------------------
__global__ __launch_bounds__(1024) void k_ssqrt(float* __restrict__ out_fm)
{
    const int b = blockIdx.x;
    float ss = 0.f;
    for (int e = threadIdx.x; e < MC; e += 1024) {
        float x = g_fmraw[b * MC + e];
        float f = (x == 0.f) ? 0.f : copysignf(sqrtf(fabsf(x) + 1e-12f), x);
        out_fm[b * MC + e] = f;
        ss += f * f;
    }
    __shared__ float red[32];
#pragma unroll
    for (int o = 16; o; o >>= 1) ss += __shfl_xor_sync(0xffffffffu, ss, o);
    if ((threadIdx.x & 31) == 0) red[threadIdx.x >> 5] = ss;
    __syncthreads();
    if (threadIdx.x < 32) {
        ss = red[threadIdx.x];
#pragma unroll
        for (int o = 16; o; o >>= 1) ss += __shfl_xor_sync(0xffffffffu, ss, o);
        if (threadIdx.x == 0) {
            float nrm = sqrtf(ss);
            float s = 1.f / fmaxf(nrm, 1e-12f);
            g_scale[b] = s;
            g_scale100[b] = 100.f * s;
        }
    }
}

// p init with bias (range version so it can be split across launches)
__global__ __launch_bounds__(256) void k_p0(const float* __restrict__ fcb,
                                            float* __restrict__ out_p,
                                            int base, int count)
{
    int i = base + blockIdx.x * 256 + threadIdx.x;
    if (i < base + count && i < Bn * NCLS) out_p[i] = __ldg(&fcb[i % NCLS]);
}

// ---------------------------------------------------------------------------
// Kernel D: p[b,n] += sum_k f_unnorm[b,k]*(100/nrm_b) * fc_w[n,k]   (split-k)
// ---------------------------------------------------------------------------
__global__ __launch_bounds__(256) void k_fc(
    const float* __restrict__ fmn, const float* __restrict__ fcw,
    float* __restrict__ out_p)
{
    __shared__ float sfm[64 * 33];
    __shared__ float sw[16 * 32];
    const int k0 = blockIdx.x * 1024;
    const int n0 = blockIdx.y * 16;
    const int t  = threadIdx.x;
    const int tb = t & 63, tg = t >> 6;

    float s100[8];
#pragma unroll
    for (int i = 0; i < 8; ++i) s100[i] = g_scale100[(t + i * 256) >> 5];

    float acc0 = 0.f, acc1 = 0.f, acc2 = 0.f, acc3 = 0.f;

    for (int kb = 0; kb < 1024; kb += 32) {
        __syncthreads();
#pragma unroll
        for (int i = 0; i < 8; ++i) {
            int e = t + i * 256;
            int bb = e >> 5, kk = e & 31;
            sfm[bb * 33 + kk] = fmn[bb * MC + k0 + kb + kk] * s100[i];
        }
#pragma unroll
        for (int i = 0; i < 2; ++i) {
            int e = t + i * 256;
            int nn = e >> 5, kk = e & 31;
            int n = n0 + nn;
            sw[nn * 32 + kk] = (n < NCLS) ? fcw[(size_t)n * MC + k0 + kb + kk] : 0.f;
        }
        __syncthreads();
#pragma unroll
        for (int kk = 0; kk < 32; ++kk) {
            float v = sfm[tb * 33 + kk];
            acc0 += v * sw[(tg * 4 + 0) * 32 + kk];
            acc1 += v * sw[(tg * 4 + 1) * 32 + kk];
            acc2 += v * sw[(tg * 4 + 2) * 32 + kk];
            acc3 += v * sw[(tg * 4 + 3) * 32 + kk];
        }
    }
    int n = n0 + tg * 4;
    if (n + 0 < NCLS) atomicAdd(&out_p[tb * NCLS + n + 0], acc0);
    if (n + 1 < NCLS) atomicAdd(&out_p[tb * NCLS + n + 1], acc1);
    if (n + 2 < NCLS) atomicAdd(&out_p[tb * NCLS + n + 2], acc2);
    if (n + 3 < NCLS) atomicAdd(&out_p[tb * NCLS + n + 3], acc3);
}

// normalize fm in place (after k_fc consumed unnormalized values)
__global__ __launch_bounds__(256) void k_norm(float* __restrict__ out_fm)
{
    int i = blockIdx.x * 256 + threadIdx.x;
    if (i < Bn * MC) out_fm[i] *= g_scale[i / MC];
}

// ---------------------------------------------------------------------------
extern "C" void kernel_launch(void* const* d_in, const int* in_sizes, int n_in,
                              void* d_out, int out_size)
{
    const float* fmap = (const float*)d_in[0];
    const float* attw = (const float*)d_in[1];
    const float* attb = (const float*)d_in[2];
    const float* fcw  = (const float*)d_in[3];
    const float* fcb  = (const float*)d_in[4];
    float* out     = (float*)d_out;
    float* out_p   = out + OFF_P;
    float* out_fm  = out + OFF_FM;
    float* out_att = out + OFF_ATT;
    (void)in_sizes; (void)n_in; (void)out_size;

    // k_p0 split in 3 so launch index 3 (the ncu capture slot) = k_att_mma.
    k_p0<<<17, 256>>>(fcb, out_p, 0,    4352);
    k_p0<<<17, 256>>>(fcb, out_p, 4352, 4352);
    k_p0<<<17, 256>>>(fcb, out_p, 8704, 4096);
    k_att_mma <<<dim3(6, 64), 256, ATT_SMEM_DYN>>>(fmap, attw, attb, out_att);
    k_pool_mma<<<dim3(6, 64), 256, POOL_SMEM_DYN>>>(fmap, out_att);
    k_ssqrt<<<Bn, 1024>>>(out_fm);
    k_fc  <<<dim3(24, 13), 256>>>(out_fm, fcw, out_p);
    k_norm<<<(Bn * MC + 255) / 256, 256>>>(out_fm);
}

// round 11
// speedup vs baseline: 3.0100x; 1.1818x over previous
#include <cuda_runtime.h>
#include <cuda_bf16.h>
#include <cstdint>

// Problem constants
#define Bn   64
#define Cc   768
#define HW   676          // 26*26
#define Mm   32
#define NCLS 200
#define MC   (Mm*Cc)      // 24576
#define OFF_P   0
#define OFF_FM  (Bn*NCLS)                  // 12800
#define OFF_ATT (OFF_FM + Bn*MC)           // 12800 + 1572864

// Scratch (no allocation allowed -> device globals).
// NEVER pass these as host-side kernel arguments — device-code use only.
__device__ float g_fmraw[Bn * MC];     // pooled bilinear features before sqrt
__device__ float g_scale[Bn];          // 1/max(||f||,eps)
__device__ float g_scale100[Bn];       // 100/max(||f||,eps)

// ===========================================================================
// Baseline-ISA tensor helpers (ldmatrix + mma.sync assemble for plain sm_103;
// tcgen05 does NOT — harness assembles a non-'a' target).
// ===========================================================================
__device__ __forceinline__ uint32_t smem_u32(const void* p) {
    uint32_t r;
    asm("{ .reg .u64 t; cvta.to.shared.u64 t, %1; cvt.u32.u64 %0, t; }"
        : "=r"(r) : "l"(p));
    return r;
}
#define SWZ128(o)  ((o) ^ (((o) >> 3) & 0x70))

__device__ __forceinline__ void ldsm_x4(uint32_t addr, uint32_t r[4]) {
    asm volatile("ldmatrix.sync.aligned.m8n8.x4.shared.b16 {%0,%1,%2,%3}, [%4];"
                 : "=r"(r[0]), "=r"(r[1]), "=r"(r[2]), "=r"(r[3]) : "r"(addr));
}
__device__ __forceinline__ void ldsm_x4_t(uint32_t addr, uint32_t r[4]) {
    asm volatile("ldmatrix.sync.aligned.m8n8.x4.trans.shared.b16 {%0,%1,%2,%3}, [%4];"
                 : "=r"(r[0]), "=r"(r[1]), "=r"(r[2]), "=r"(r[3]) : "r"(addr));
}
__device__ __forceinline__ void mma_bf16(float* c, const uint32_t a[4],
                                         uint32_t b0, uint32_t b1) {
    asm volatile(
        "mma.sync.aligned.m16n8k16.row.col.f32.bf16.bf16.f32 "
        "{%0,%1,%2,%3}, {%4,%5,%6,%7}, {%8,%9}, {%0,%1,%2,%3};"
        : "+f"(c[0]), "+f"(c[1]), "+f"(c[2]), "+f"(c[3])
        : "r"(a[0]), "r"(a[1]), "r"(a[2]), "r"(a[3]), "r"(b0), "r"(b1));
}

__device__ __forceinline__ void split_pack(float x, float y,
                                           uint32_t& hi, uint32_t& lo) {
    __nv_bfloat16 hx = __float2bfloat16_rn(x);
    __nv_bfloat16 hy = __float2bfloat16_rn(y);
    __nv_bfloat16 lx = __float2bfloat16_rn(x - __bfloat162float(hx));
    __nv_bfloat16 ly = __float2bfloat16_rn(y - __bfloat162float(hy));
    hi = ((uint32_t)__bfloat16_as_ushort(hy) << 16) | __bfloat16_as_ushort(hx);
    lo = ((uint32_t)__bfloat16_as_ushort(ly) << 16) | __bfloat16_as_ushort(lx);
}

// ---------------------------------------------------------------------------
// Kernel A (mma.sync, double-buffered): att = relu(W @ X + bias)
// Per CTA (hw-tile 128, batch b): D[32m x 128hw], K = c in 12 chunks of 64.
// A = W K-major SW128 -> non-trans ldmatrix; B = X [c][hw] pitch 136 bf16 ->
// trans ldmatrix. bf16 hi/lo split, 3 products, fp32 accum.
// Pipeline per chunk: LDG(ch+1) -> mma(buf[ch&1]) -> cvt+STS(buf[~ch&1]) -> sync.
// ---------------------------------------------------------------------------
#define KCH      64
#define NKCH     12
#define PXB      272                    // X row pitch bytes (136 bf16)
#define X_HI_OFF 0                      // 64*272 = 17408
#define X_LO_OFF 17408
#define W_HI_OFF 34816                  // 34*1024 (SW128 region 1024-aligned)
#define W_LO_OFF 38912
#define ATT_BUF  43008                  // 42*1024 (keeps buffer1 1024-aligned)
#define ATT_SMEM_DYN (2 * ATT_BUF + 1024)

__global__ __launch_bounds__(256, 2) void k_att_mma(
    const float* __restrict__ fmap, const float* __restrict__ attw,
    const float* __restrict__ attb, float* __restrict__ out_att)
{
    extern __shared__ char dyn_smem[];
    const int b   = blockIdx.y;
    const int hwt = blockIdx.x * 128;
    const int t   = threadIdx.x;
    const int w   = t >> 5, lane = t & 31;

    uint32_t raw = smem_u32(dyn_smem);
    uint32_t abase = (raw + 1023u) & ~1023u;
    char* sbuf = dyn_smem + (abase - raw);

    const float* X = fmap + (size_t)b * Cc * HW;

    float acc[2][2][4];
#pragma unroll
    for (int mt = 0; mt < 2; ++mt)
#pragma unroll
        for (int nt = 0; nt < 2; ++nt)
#pragma unroll
            for (int j = 0; j < 4; ++j) acc[mt][nt][j] = 0.f;

    // lane-constant ldmatrix bases
    const int r8 = lane & 7;
    const int aRowIn = ((lane >> 3) & 1) * 8 + r8;
    const int aColB  = ((lane >> 4) & 1) * 16;
    const int bKrow  = lane & 15;
    const int bNcol  = w * 16 + ((lane >> 4) & 1) * 8;

    // staging registers
    float4 xv[8], wv[2];

    // per-thread staging coords (fixed across chunks)
    const int xrow[8] = { (t) >> 5, (t + 256) >> 5, (t + 512) >> 5, (t + 768) >> 5,
                          (t + 1024) >> 5, (t + 1280) >> 5, (t + 1536) >> 5, (t + 1792) >> 5 };
    const int xqc  = t & 31;
    const int xhw  = hwt + xqc * 4;
    const bool xok = xhw < HW;          // HW%4==0 -> whole quad in range
    const int wrow[2] = { t >> 4, (t + 256) >> 4 };
    const int wqc  = t & 15;

#define ATT_LOAD(c0_)                                                         \
    do {                                                                      \
        _Pragma("unroll")                                                     \
        for (int i = 0; i < 8; ++i)                                           \
            xv[i] = xok ? *(const float4*)(X + (size_t)((c0_) + xrow[i]) * HW + xhw) \
                        : make_float4(0.f, 0.f, 0.f, 0.f);                    \
        _Pragma("unroll")                                                     \
        for (int i = 0; i < 2; ++i)                                           \
            wv[i] = *(const float4*)(attw + (size_t)wrow[i] * Cc + (c0_) + wqc * 4); \
    } while (0)

#define ATT_STORE(dst_)                                                       \
    do {                                                                      \
        char* db_ = (dst_);                                                   \
        _Pragma("unroll")                                                     \
        for (int i = 0; i < 8; ++i) {                                         \
            uint32_t h01, l01, h23, l23;                                      \
            split_pack(xv[i].x, xv[i].y, h01, l01);                           \
            split_pack(xv[i].z, xv[i].w, h23, l23);                           \
            uint32_t off = (uint32_t)(xrow[i] * PXB + xqc * 8);               \
            *(uint32_t*)(db_ + X_HI_OFF + off)     = h01;                     \
            *(uint32_t*)(db_ + X_HI_OFF + off + 4) = h23;                     \
            *(uint32_t*)(db_ + X_LO_OFF + off)     = l01;                     \
            *(uint32_t*)(db_ + X_LO_OFF + off + 4) = l23;                     \
        }                                                                     \
        _Pragma("unroll")                                                     \
        for (int i = 0; i < 2; ++i) {                                         \
            uint32_t h01, l01, h23, l23;                                      \
            split_pack(wv[i].x, wv[i].y, h01, l01);                           \
            split_pack(wv[i].z, wv[i].w, h23, l23);                           \
            uint32_t off = SWZ128((uint32_t)(wrow[i] * 128 + wqc * 8));       \
            *(uint32_t*)(db_ + W_HI_OFF + off)     = h01;                     \
            *(uint32_t*)(db_ + W_HI_OFF + off + 4) = h23;                     \
            *(uint32_t*)(db_ + W_LO_OFF + off)     = l01;                     \
            *(uint32_t*)(db_ + W_LO_OFF + off + 4) = l23;                     \
        }                                                                     \
    } while (0)

    // prologue: chunk 0
    ATT_LOAD(0);
    ATT_STORE(sbuf);
    __syncthreads();

    for (int ch = 0; ch < NKCH; ++ch) {
        const uint32_t abuf = abase + (uint32_t)(ch & 1) * ATT_BUF;
        if (ch + 1 < NKCH) ATT_LOAD((ch + 1) * KCH);   // LDG in flight over mma

#pragma unroll
        for (int ks = 0; ks < 4; ++ks) {
            uint32_t ah[2][4], al[2][4];
#pragma unroll
            for (int mt = 0; mt < 2; ++mt) {
                uint32_t aOff = SWZ128((uint32_t)((mt * 16 + aRowIn) * 128 +
                                                  ks * 32 + aColB));
                ldsm_x4(abuf + W_HI_OFF + aOff, ah[mt]);
                ldsm_x4(abuf + W_LO_OFF + aOff, al[mt]);
            }
            uint32_t bOff = (uint32_t)((ks * 16 + bKrow) * PXB + bNcol * 2);
            uint32_t bh[4], bl[4];
            ldsm_x4_t(abuf + X_HI_OFF + bOff, bh);
            ldsm_x4_t(abuf + X_LO_OFF + bOff, bl);
#pragma unroll
            for (int mt = 0; mt < 2; ++mt)
#pragma unroll
                for (int nt = 0; nt < 2; ++nt) {
                    mma_bf16(acc[mt][nt], ah[mt], bh[2 * nt], bh[2 * nt + 1]);
                    mma_bf16(acc[mt][nt], ah[mt], bl[2 * nt], bl[2 * nt + 1]);
                    mma_bf16(acc[mt][nt], al[mt], bh[2 * nt], bh[2 * nt + 1]);
                }
        }

        if (ch + 1 < NKCH) ATT_STORE(sbuf + ((ch + 1) & 1) * ATT_BUF);
        __syncthreads();
    }

    // epilogue: relu(acc + bias)
    float* ob = out_att + (size_t)b * Mm * HW;
#pragma unroll
    for (int mt = 0; mt < 2; ++mt) {
        const int m  = mt * 16 + (lane >> 2);
        const float bs0 = __ldg(&attb[m]);
        const float bs8 = __ldg(&attb[m + 8]);
#pragma unroll
        for (int nt = 0; nt < 2; ++nt) {
            int hwc = hwt + w * 16 + nt * 8 + 2 * (lane & 3);
            if (hwc + 1 < HW) {
                ob[(size_t)m * HW + hwc]           = fmaxf(acc[mt][nt][0] + bs0, 0.f);
                ob[(size_t)m * HW + hwc + 1]       = fmaxf(acc[mt][nt][1] + bs0, 0.f);
                ob[(size_t)(m + 8) * HW + hwc]     = fmaxf(acc[mt][nt][2] + bs8, 0.f);
                ob[(size_t)(m + 8) * HW + hwc + 1] = fmaxf(acc[mt][nt][3] + bs8, 0.f);
            }
        }
    }
#undef ATT_LOAD
#undef ATT_STORE
}

// ---------------------------------------------------------------------------
// Kernel B (mma.sync, double-buffered): g_fmraw = (1/676) att @ fm^T
// Per CTA (c-tile 128, batch b): D[128c x 32m], K = hw in 11 chunks of 64.
// Both operands K-major SW128 -> non-trans ldmatrix.
// ---------------------------------------------------------------------------
#define CH       64
#define NCHUNK   11
#define A_HI_OFF 0
#define A_LO_OFF 16384
#define B_HI_OFF 32768
#define B_LO_OFF 36864
#define POOL_BUF 40960                  // 40*1024
#define POOL_SMEM_DYN (2 * POOL_BUF + 1024)

__global__ __launch_bounds__(256, 2) void k_pool_mma(
    const float* __restrict__ fmap, const float* __restrict__ att)
{
    extern __shared__ char dyn_smem[];

    const int b  = blockIdx.y;
    const int c0 = blockIdx.x * 128;
    const int t  = threadIdx.x;
    const int w  = t >> 5, lane = t & 31;
    const int rw = w * 16;

    uint32_t raw = smem_u32(dyn_smem);
    uint32_t abase = (raw + 1023u) & ~1023u;
    char* sbuf = dyn_smem + (abase - raw);

    const float* Aruns = fmap + (size_t)(b * Cc + c0) * HW;
    const float* Bruns = att  + (size_t)b * Mm * HW;

    float acc[4][4];
#pragma unroll
    for (int p = 0; p < 4; ++p)
#pragma unroll
        for (int j = 0; j < 4; ++j) acc[p][j] = 0.f;

    const int r8   = lane & 7;
    const int aRow = rw + ((lane >> 3) & 1) * 8 + r8;
    const int aColM = ((lane >> 4) & 1) * 16;
    const int bRow0 = ((lane >> 4) & 1) * 8 + r8;
    const int bColM = ((lane >> 3) & 1) * 16;

    float4 av[8], bv[2];
    const int arow[8] = { (t) >> 4, (t + 256) >> 4, (t + 512) >> 4, (t + 768) >> 4,
                          (t + 1024) >> 4, (t + 1280) >> 4, (t + 1536) >> 4, (t + 1792) >> 4 };
    const int aqc = t & 15;             // k-quad within 64

#define POOL_LOAD(hw0_)                                                       \
    do {                                                                      \
        const int hwq_ = (hw0_) + aqc * 4;                                    \
        const bool ok_ = hwq_ + 3 < HW;                                       \
        _Pragma("unroll")                                                     \
        for (int i = 0; i < 8; ++i)                                           \
            av[i] = ok_ ? *(const float4*)(Aruns + (size_t)arow[i] * HW + hwq_) \
                        : make_float4(0.f, 0.f, 0.f, 0.f);                    \
        _Pragma("unroll")                                                     \
        for (int i = 0; i < 2; ++i) {                                         \
            int row_ = (t + i * 256) >> 4;                                    \
            bv[i] = ok_ ? *(const float4*)(Bruns + (size_t)row_ * HW + hwq_)  \
                        : make_float4(0.f, 0.f, 0.f, 0.f);                    \
        }                                                                     \
    } while (0)

#define POOL_STORE(dst_)                                                      \
    do {                                                                      \
        char* db_ = (dst_);                                                   \
        _Pragma("unroll")                                                     \
        for (int i = 0; i < 8; ++i) {                                         \
            uint32_t h01, l01, h23, l23;                                      \
            split_pack(av[i].x, av[i].y, h01, l01);                           \
            split_pack(av[i].z, av[i].w, h23, l23);                           \
            uint32_t off = SWZ128((uint32_t)(arow[i] * 128 + aqc * 8));       \
            *(uint32_t*)(db_ + A_HI_OFF + off)     = h01;                     \
            *(uint32_t*)(db_ + A_HI_OFF + off + 4) = h23;                     \
            *(uint32_t*)(db_ + A_LO_OFF + off)     = l01;                     \
            *(uint32_t*)(db_ + A_LO_OFF + off + 4) = l23;                     \
        }                                                                     \
        _Pragma("unroll")                                                     \
        for (int i = 0; i < 2; ++i) {                                         \
            int row_ = (t + i * 256) >> 4;                                    \
            uint32_t h01, l01, h23, l23;                                      \
            split_pack(bv[i].x, bv[i].y, h01, l01);                           \
            split_pack(bv[i].z, bv[i].w, h23, l23);                           \
            uint32_t off = SWZ128((uint32_t)(row_ * 128 + aqc * 8));          \
            *(uint32_t*)(db_ + B_HI_OFF + off)     = h01;                     \
            *(uint32_t*)(db_ + B_HI_OFF + off + 4) = h23;                     \
            *(uint32_t*)(db_ + B_LO_OFF + off)     = l01;                     \
            *(uint32_t*)(db_ + B_LO_OFF + off + 4) = l23;                     \
        }                                                                     \
    } while (0)

    POOL_LOAD(0);
    POOL_STORE(sbuf);
    __syncthreads();

    for (int chunk = 0; chunk < NCHUNK; ++chunk) {
        const uint32_t abuf = abase + (uint32_t)(chunk & 1) * POOL_BUF;
        if (chunk + 1 < NCHUNK) POOL_LOAD((chunk + 1) * CH);

#pragma unroll
        for (int ks = 0; ks < 4; ++ks) {
            const uint32_t aOff = SWZ128((uint32_t)(aRow * 128 + ks * 32 + aColM));
            uint32_t ah[4], al[4];
            ldsm_x4(abuf + A_HI_OFF + aOff, ah);
            ldsm_x4(abuf + A_LO_OFF + aOff, al);
#pragma unroll
            for (int pp = 0; pp < 2; ++pp) {
                const uint32_t bOff =
                    SWZ128((uint32_t)((pp * 16 + bRow0) * 128 + ks * 32 + bColM));
                uint32_t bh[4], bl[4];
                ldsm_x4(abuf + B_HI_OFF + bOff, bh);   // NON-trans (K-major B)
                ldsm_x4(abuf + B_LO_OFF + bOff, bl);
                mma_bf16(acc[2 * pp],     ah, bh[0], bh[1]);
                mma_bf16(acc[2 * pp],     ah, bl[0], bl[1]);
                mma_bf16(acc[2 * pp],     al, bh[0], bh[1]);
                mma_bf16(acc[2 * pp + 1], ah, bh[2], bh[3]);
                mma_bf16(acc[2 * pp + 1], ah, bl[2], bl[3]);
                mma_bf16(acc[2 * pp + 1], al, bh[2], bh[3]);
            }
        }

        if (chunk + 1 < NCHUNK) POOL_STORE(sbuf + ((chunk + 1) & 1) * POOL_BUF);
        __syncthreads();
    }

    const float inv = 1.f / (float)HW;
    const int crow = c0 + rw + (lane >> 2);
#pragma unroll
    for (int p = 0; p < 4; ++p) {
        const int n = p * 8 + (lane & 3) * 2;
        g_fmraw[((size_t)b * Mm + n)     * Cc + crow]     = acc[p][0] * inv;
        g_fmraw[((size_t)b * Mm + n + 1) * Cc + crow]     = acc[p][1] * inv;
        g_fmraw[((size_t)b * Mm + n)     * Cc + crow + 8] = acc[p][2] * inv;
        g_fmraw[((size_t)b * Mm + n + 1) * Cc + crow + 8] = acc[p][3] * inv;
    }
#undef POOL_LOAD
#undef POOL_STORE
}

// ---------------------------------------------------------------------------
// Kernel C: f = sign(x)*sqrt(|x|+eps); unnormalized f -> out_fm;
// per-batch sumsq -> g_scale / g_scale100.
// ---------------------------------------------------------------------------
__global__ __launch_bounds__(1024) void k_ssqrt(float* __restrict__ out_fm)
{
    const int b = blockIdx.x;
    float ss = 0.f;
    for (int e = threadIdx.x; e < MC; e += 1024) {
        float x = g_fmraw[b * MC + e];
        float f = (x == 0.f) ? 0.f : copysignf(sqrtf(fabsf(x) + 1e-12f), x);
        out_fm[b * MC + e] = f;
        ss += f * f;
    }
    __shared__ float red[32];
#pragma unroll
    for (int o = 16; o; o >>= 1) ss += __shfl_xor_sync(0xffffffffu, ss, o);
    if ((threadIdx.x & 31) == 0) red[threadIdx.x >> 5] = ss;
    __syncthreads();
    if (threadIdx.x < 32) {
        ss = red[threadIdx.x];
#pragma unroll
        for (int o = 16; o; o >>= 1) ss += __shfl_xor_sync(0xffffffffu, ss, o);
        if (threadIdx.x == 0) {
            float nrm = sqrtf(ss);
            float s = 1.f / fmaxf(nrm, 1e-12f);
            g_scale[b] = s;
            g_scale100[b] = 100.f * s;
        }
    }
}

// p init with bias (range version; split across launches for ncu slot aiming)
__global__ __launch_bounds__(256) void k_p0(const float* __restrict__ fcb,
                                            float* __restrict__ out_p,
                                            int base, int count)
{
    int i = base + blockIdx.x * 256 + threadIdx.x;
    if (i < base + count && i < Bn * NCLS) out_p[i] = __ldg(&fcb[i % NCLS]);
}

// ---------------------------------------------------------------------------
// Kernel D: p[b,n] += sum_k f_unnorm[b,k]*(100/nrm_b) * fc_w[n,k]   (split-k)
// ---------------------------------------------------------------------------
__global__ __launch_bounds__(256) void k_fc(
    const float* __restrict__ fmn, const float* __restrict__ fcw,
    float* __restrict__ out_p)
{
    __shared__ float sfm[64 * 33];
    __shared__ float sw[16 * 32];
    const int k0 = blockIdx.x * 1024;
    const int n0 = blockIdx.y * 16;
    const int t  = threadIdx.x;
    const int tb = t & 63, tg = t >> 6;

    float s100[8];
#pragma unroll
    for (int i = 0; i < 8; ++i) s100[i] = g_scale100[(t + i * 256) >> 5];

    float acc0 = 0.f, acc1 = 0.f, acc2 = 0.f, acc3 = 0.f;

    for (int kb = 0; kb < 1024; kb += 32) {
        __syncthreads();
#pragma unroll
        for (int i = 0; i < 8; ++i) {
            int e = t + i * 256;
            int bb = e >> 5, kk = e & 31;
            sfm[bb * 33 + kk] = fmn[bb * MC + k0 + kb + kk] * s100[i];
        }
#pragma unroll
        for (int i = 0; i < 2; ++i) {
            int e = t + i * 256;
            int nn = e >> 5, kk = e & 31;
            int n = n0 + nn;
            sw[nn * 32 + kk] = (n < NCLS) ? fcw[(size_t)n * MC + k0 + kb + kk] : 0.f;
        }
        __syncthreads();
#pragma unroll
        for (int kk = 0; kk < 32; ++kk) {
            float v = sfm[tb * 33 + kk];
            acc0 += v * sw[(tg * 4 + 0) * 32 + kk];
            acc1 += v * sw[(tg * 4 + 1) * 32 + kk];
            acc2 += v * sw[(tg * 4 + 2) * 32 + kk];
            acc3 += v * sw[(tg * 4 + 3) * 32 + kk];
        }
    }
    int n = n0 + tg * 4;
    if (n + 0 < NCLS) atomicAdd(&out_p[tb * NCLS + n + 0], acc0);
    if (n + 1 < NCLS) atomicAdd(&out_p[tb * NCLS + n + 1], acc1);
    if (n + 2 < NCLS) atomicAdd(&out_p[tb * NCLS + n + 2], acc2);
    if (n + 3 < NCLS) atomicAdd(&out_p[tb * NCLS + n + 3], acc3);
}

// normalize fm in place (after k_fc consumed unnormalized values)
__global__ __launch_bounds__(256) void k_norm(float* __restrict__ out_fm)
{
    int i = blockIdx.x * 256 + threadIdx.x;
    if (i < Bn * MC) out_fm[i] *= g_scale[i / MC];
}

// ---------------------------------------------------------------------------
extern "C" void kernel_launch(void* const* d_in, const int* in_sizes, int n_in,
                              void* d_out, int out_size)
{
    const float* fmap = (const float*)d_in[0];
    const float* attw = (const float*)d_in[1];
    const float* attb = (const float*)d_in[2];
    const float* fcw  = (const float*)d_in[3];
    const float* fcb  = (const float*)d_in[4];
    float* out     = (float*)d_out;
    float* out_p   = out + OFF_P;
    float* out_fm  = out + OFF_FM;
    float* out_att = out + OFF_ATT;
    (void)in_sizes; (void)n_in; (void)out_size;

    // >48KB dynamic smem opt-in (attribute set, not an allocation; idempotent)
    cudaFuncSetAttribute(k_att_mma,  cudaFuncAttributeMaxDynamicSharedMemorySize,
                         ATT_SMEM_DYN);
    cudaFuncSetAttribute(k_pool_mma, cudaFuncAttributeMaxDynamicSharedMemorySize,
                         POOL_SMEM_DYN);

    // Launch order: idx 3 (ncu capture slot) = k_pool_mma this round.
    k_p0<<<25, 256>>>(fcb, out_p, 0,    6400);
    k_att_mma <<<dim3(6, 64), 256, ATT_SMEM_DYN>>>(fmap, attw, attb, out_att);
    k_p0<<<25, 256>>>(fcb, out_p, 6400, 6400);
    k_pool_mma<<<dim3(6, 64), 256, POOL_SMEM_DYN>>>(fmap, out_att);
    k_ssqrt<<<Bn, 1024>>>(out_fm);
    k_fc  <<<dim3(24, 13), 256>>>(out_fm, fcw, out_p);
    k_norm<<<(Bn * MC + 255) / 256, 256>>>(out_fm);
}

// round 12
// speedup vs baseline: 4.5393x; 1.5081x over previous
#include <cuda_runtime.h>
#include <cuda_bf16.h>
#include <cstdint>

// Problem constants
#define Bn   64
#define Cc   768
#define HW   676          // 26*26
#define Mm   32
#define NCLS 200
#define MC   (Mm*Cc)      // 24576
#define OFF_P   0
#define OFF_FM  (Bn*NCLS)                  // 12800
#define OFF_ATT (OFF_FM + Bn*MC)           // 12800 + 1572864

// Scratch (no allocation allowed -> device global; device-code use only).
__device__ float g_fmraw[Bn * MC];     // pooled bilinear features before sqrt

// ===========================================================================
// Baseline-ISA tensor helpers (ldmatrix + mma.sync assemble for plain sm_103;
// tcgen05 does NOT — harness assembles a non-'a' target).
// ===========================================================================
__device__ __forceinline__ uint32_t smem_u32(const void* p) {
    uint32_t r;
    asm("{ .reg .u64 t; cvta.to.shared.u64 t, %1; cvt.u32.u64 %0, t; }"
        : "=r"(r) : "l"(p));
    return r;
}
#define SWZ128(o)  ((o) ^ (((o) >> 3) & 0x70))

__device__ __forceinline__ void ldsm_x4(uint32_t addr, uint32_t r[4]) {
    asm volatile("ldmatrix.sync.aligned.m8n8.x4.shared.b16 {%0,%1,%2,%3}, [%4];"
                 : "=r"(r[0]), "=r"(r[1]), "=r"(r[2]), "=r"(r[3]) : "r"(addr));
}
__device__ __forceinline__ void ldsm_x4_t(uint32_t addr, uint32_t r[4]) {
    asm volatile("ldmatrix.sync.aligned.m8n8.x4.trans.shared.b16 {%0,%1,%2,%3}, [%4];"
                 : "=r"(r[0]), "=r"(r[1]), "=r"(r[2]), "=r"(r[3]) : "r"(addr));
}
__device__ __forceinline__ void mma_bf16(float* c, const uint32_t a[4],
                                         uint32_t b0, uint32_t b1) {
    asm volatile(
        "mma.sync.aligned.m16n8k16.row.col.f32.bf16.bf16.f32 "
        "{%0,%1,%2,%3}, {%4,%5,%6,%7}, {%8,%9}, {%0,%1,%2,%3};"
        : "+f"(c[0]), "+f"(c[1]), "+f"(c[2]), "+f"(c[3])
        : "r"(a[0]), "r"(a[1]), "r"(a[2]), "r"(a[3]), "r"(b0), "r"(b1));
}

// hi/lo bf16 split of a float pair: 1 packed cvt for hi, bit-ops to rebuild
// hi as fp32 (bf16->fp32 is <<16), exact residual, 1 packed cvt for lo.
// (x - hi(x) is exactly representable in fp32 -> identical math to the old
//  4-cvt/2-sub/2-pack version, ~25% fewer issue slots.)
__device__ __forceinline__ void split_pack(float x, float y,
                                           uint32_t& hi, uint32_t& lo) {
    __nv_bfloat162 h2 = __floats2bfloat162_rn(x, y);    // x -> low half
    uint32_t h = *(uint32_t*)&h2;
    float hx = __uint_as_float(h << 16);
    float hy = __uint_as_float(h & 0xFFFF0000u);
    __nv_bfloat162 l2 = __floats2bfloat162_rn(x - hx, y - hy);
    hi = h;
    lo = *(uint32_t*)&l2;
}

// ---------------------------------------------------------------------------
// Kernel A (mma.sync, double-buffered): att = relu(W @ X + bias)
// Per CTA (hw-tile 128, batch b): D[32m x 128hw], K = c in 12 chunks of 64.
// A = W K-major SW128 -> non-trans ldmatrix; B = X [c][hw] pitch 136 bf16 ->
// trans ldmatrix. bf16 hi/lo split, 3 products, fp32 accum.
// ---------------------------------------------------------------------------
#define KCH      64
#define NKCH     12
#define PXB      272                    // X row pitch bytes (136 bf16)
#define X_HI_OFF 0                      // 64*272 = 17408
#define X_LO_OFF 17408
#define W_HI_OFF 34816                  // 34*1024 (SW128 region 1024-aligned)
#define W_LO_OFF 38912
#define ATT_BUF  43008                  // 42*1024 (keeps buffer1 1024-aligned)
#define ATT_SMEM_DYN (2 * ATT_BUF + 1024)

__global__ __launch_bounds__(256, 2) void k_att_mma(
    const float* __restrict__ fmap, const float* __restrict__ attw,
    const float* __restrict__ attb, float* __restrict__ out_att)
{
    extern __shared__ char dyn_smem[];
    const int b   = blockIdx.y;
    const int hwt = blockIdx.x * 128;
    const int t   = threadIdx.x;
    const int w   = t >> 5, lane = t & 31;

    uint32_t raw = smem_u32(dyn_smem);
    uint32_t abase = (raw + 1023u) & ~1023u;
    char* sbuf = dyn_smem + (abase - raw);

    const float* X = fmap + (size_t)b * Cc * HW;

    float acc[2][2][4];
#pragma unroll
    for (int mt = 0; mt < 2; ++mt)
#pragma unroll
        for (int nt = 0; nt < 2; ++nt)
#pragma unroll
            for (int j = 0; j < 4; ++j) acc[mt][nt][j] = 0.f;

    const int r8 = lane & 7;
    const int aRowIn = ((lane >> 3) & 1) * 8 + r8;
    const int aColB  = ((lane >> 4) & 1) * 16;
    const int bKrow  = lane & 15;
    const int bNcol  = w * 16 + ((lane >> 4) & 1) * 8;

    float4 xv[8], wv[2];
    const int xrow[8] = { (t) >> 5, (t + 256) >> 5, (t + 512) >> 5, (t + 768) >> 5,
                          (t + 1024) >> 5, (t + 1280) >> 5, (t + 1536) >> 5, (t + 1792) >> 5 };
    const int xqc  = t & 31;
    const int xhw  = hwt + xqc * 4;
    const bool xok = xhw < HW;          // HW%4==0 -> whole quad in range
    const int wrow[2] = { t >> 4, (t + 256) >> 4 };
    const int wqc  = t & 15;

#define ATT_LOAD(c0_)                                                         \
    do {                                                                      \
        _Pragma("unroll")                                                     \
        for (int i = 0; i < 8; ++i)                                           \
            xv[i] = xok ? *(const float4*)(X + (size_t)((c0_) + xrow[i]) * HW + xhw) \
                        : make_float4(0.f, 0.f, 0.f, 0.f);                    \
        _Pragma("unroll")                                                     \
        for (int i = 0; i < 2; ++i)                                           \
            wv[i] = *(const float4*)(attw + (size_t)wrow[i] * Cc + (c0_) + wqc * 4); \
    } while (0)

#define ATT_STORE(dst_)                                                       \
    do {                                                                      \
        char* db_ = (dst_);                                                   \
        _Pragma("unroll")                                                     \
        for (int i = 0; i < 8; ++i) {                                         \
            uint32_t h01, l01, h23, l23;                                      \
            split_pack(xv[i].x, xv[i].y, h01, l01);                           \
            split_pack(xv[i].z, xv[i].w, h23, l23);                           \
            uint32_t off = (uint32_t)(xrow[i] * PXB + xqc * 8);               \
            *(uint2*)(db_ + X_HI_OFF + off) = make_uint2(h01, h23);           \
            *(uint2*)(db_ + X_LO_OFF + off) = make_uint2(l01, l23);           \
        }                                                                     \
        _Pragma("unroll")                                                     \
        for (int i = 0; i < 2; ++i) {                                         \
            uint32_t h01, l01, h23, l23;                                      \
            split_pack(wv[i].x, wv[i].y, h01, l01);                           \
            split_pack(wv[i].z, wv[i].w, h23, l23);                           \
            uint32_t off = SWZ128((uint32_t)(wrow[i] * 128 + wqc * 8));       \
            *(uint2*)(db_ + W_HI_OFF + off) = make_uint2(h01, h23);           \
            *(uint2*)(db_ + W_LO_OFF + off) = make_uint2(l01, l23);           \
        }                                                                     \
    } while (0)

    ATT_LOAD(0);
    ATT_STORE(sbuf);
    __syncthreads();

    for (int ch = 0; ch < NKCH; ++ch) {
        const uint32_t abuf = abase + (uint32_t)(ch & 1) * ATT_BUF;
        if (ch + 1 < NKCH) ATT_LOAD((ch + 1) * KCH);   // LDG in flight over mma

#pragma unroll
        for (int ks = 0; ks < 4; ++ks) {
            uint32_t ah[2][4], al[2][4];
#pragma unroll
            for (int mt = 0; mt < 2; ++mt) {
                uint32_t aOff = SWZ128((uint32_t)((mt * 16 + aRowIn) * 128 +
                                                  ks * 32 + aColB));
                ldsm_x4(abuf + W_HI_OFF + aOff, ah[mt]);
                ldsm_x4(abuf + W_LO_OFF + aOff, al[mt]);
            }
            uint32_t bOff = (uint32_t)((ks * 16 + bKrow) * PXB + bNcol * 2);
            uint32_t bh[4], bl[4];
            ldsm_x4_t(abuf + X_HI_OFF + bOff, bh);
            ldsm_x4_t(abuf + X_LO_OFF + bOff, bl);
#pragma unroll
            for (int mt = 0; mt < 2; ++mt)
#pragma unroll
                for (int nt = 0; nt < 2; ++nt) {
                    mma_bf16(acc[mt][nt], ah[mt], bh[2 * nt], bh[2 * nt + 1]);
                    mma_bf16(acc[mt][nt], ah[mt], bl[2 * nt], bl[2 * nt + 1]);
                    mma_bf16(acc[mt][nt], al[mt], bh[2 * nt], bh[2 * nt + 1]);
                }
        }

        if (ch + 1 < NKCH) ATT_STORE(sbuf + ((ch + 1) & 1) * ATT_BUF);
        __syncthreads();
    }

    float* ob = out_att + (size_t)b * Mm * HW;
#pragma unroll
    for (int mt = 0; mt < 2; ++mt) {
        const int m  = mt * 16 + (lane >> 2);
        const float bs0 = __ldg(&attb[m]);
        const float bs8 = __ldg(&attb[m + 8]);
#pragma unroll
        for (int nt = 0; nt < 2; ++nt) {
            int hwc = hwt + w * 16 + nt * 8 + 2 * (lane & 3);
            if (hwc + 1 < HW) {
                ob[(size_t)m * HW + hwc]           = fmaxf(acc[mt][nt][0] + bs0, 0.f);
                ob[(size_t)m * HW + hwc + 1]       = fmaxf(acc[mt][nt][1] + bs0, 0.f);
                ob[(size_t)(m + 8) * HW + hwc]     = fmaxf(acc[mt][nt][2] + bs8, 0.f);
                ob[(size_t)(m + 8) * HW + hwc + 1] = fmaxf(acc[mt][nt][3] + bs8, 0.f);
            }
        }
    }
#undef ATT_LOAD
#undef ATT_STORE
}

// ---------------------------------------------------------------------------
// Kernel B (mma.sync, double-buffered): g_fmraw = (1/676) att @ fm^T
// Per CTA (c-tile 128, batch b): D[128c x 32m], K = hw in 11 chunks of 64.
// Both operands K-major SW128 -> non-trans ldmatrix.
// ---------------------------------------------------------------------------
#define CH       64
#define NCHUNK   11
#define A_HI_OFF 0
#define A_LO_OFF 16384
#define B_HI_OFF 32768
#define B_LO_OFF 36864
#define POOL_BUF 40960                  // 40*1024
#define POOL_SMEM_DYN (2 * POOL_BUF + 1024)

__global__ __launch_bounds__(256, 2) void k_pool_mma(
    const float* __restrict__ fmap, const float* __restrict__ att)
{
    extern __shared__ char dyn_smem[];

    const int b  = blockIdx.y;
    const int c0 = blockIdx.x * 128;
    const int t  = threadIdx.x;
    const int w  = t >> 5, lane = t & 31;
    const int rw = w * 16;

    uint32_t raw = smem_u32(dyn_smem);
    uint32_t abase = (raw + 1023u) & ~1023u;
    char* sbuf = dyn_smem + (abase - raw);

    const float* Aruns = fmap + (size_t)(b * Cc + c0) * HW;
    const float* Bruns = att  + (size_t)b * Mm * HW;

    float acc[4][4];
#pragma unroll
    for (int p = 0; p < 4; ++p)
#pragma unroll
        for (int j = 0; j < 4; ++j) acc[p][j] = 0.f;

    const int r8   = lane & 7;
    const int aRow = rw + ((lane >> 3) & 1) * 8 + r8;
    const int aColM = ((lane >> 4) & 1) * 16;
    const int bRow0 = ((lane >> 4) & 1) * 8 + r8;
    const int bColM = ((lane >> 3) & 1) * 16;

    float4 av[8], bv[2];
    const int arow[8] = { (t) >> 4, (t + 256) >> 4, (t + 512) >> 4, (t + 768) >> 4,
                          (t + 1024) >> 4, (t + 1280) >> 4, (t + 1536) >> 4, (t + 1792) >> 4 };
    const int aqc = t & 15;

#define POOL_LOAD(hw0_)                                                       \
    do {                                                                      \
        const int hwq_ = (hw0_) + aqc * 4;                                    \
        const bool ok_ = hwq_ + 3 < HW;                                       \
        _Pragma("unroll")                                                     \
        for (int i = 0; i < 8; ++i)                                           \
            av[i] = ok_ ? *(const float4*)(Aruns + (size_t)arow[i] * HW + hwq_) \
                        : make_float4(0.f, 0.f, 0.f, 0.f);                    \
        _Pragma("unroll")                                                     \
        for (int i = 0; i < 2; ++i) {                                         \
            int row_ = (t + i * 256) >> 4;                                    \
            bv[i] = ok_ ? *(const float4*)(Bruns + (size_t)row_ * HW + hwq_)  \
                        : make_float4(0.f, 0.f, 0.f, 0.f);                    \
        }                                                                     \
    } while (0)

#define POOL_STORE(dst_)                                                      \
    do {                                                                      \
        char* db_ = (dst_);                                                   \
        _Pragma("unroll")                                                     \
        for (int i = 0; i < 8; ++i) {                                         \
            uint32_t h01, l01, h23, l23;                                      \
            split_pack(av[i].x, av[i].y, h01, l01);                           \
            split_pack(av[i].z, av[i].w, h23, l23);                           \
            uint32_t off = SWZ128((uint32_t)(arow[i] * 128 + aqc * 8));       \
            *(uint2*)(db_ + A_HI_OFF + off) = make_uint2(h01, h23);           \
            *(uint2*)(db_ + A_LO_OFF + off) = make_uint2(l01, l23);           \
        }                                                                     \
        _Pragma("unroll")                                                     \
        for (int i = 0; i < 2; ++i) {                                         \
            int row_ = (t + i * 256) >> 4;                                    \
            uint32_t h01, l01, h23, l23;                                      \
            split_pack(bv[i].x, bv[i].y, h01, l01);                           \
            split_pack(bv[i].z, bv[i].w, h23, l23);                           \
            uint32_t off = SWZ128((uint32_t)(row_ * 128 + aqc * 8));          \
            *(uint2*)(db_ + B_HI_OFF + off) = make_uint2(h01, h23);           \
            *(uint2*)(db_ + B_LO_OFF + off) = make_uint2(l01, l23);           \
        }                                                                     \
    } while (0)

    POOL_LOAD(0);
    POOL_STORE(sbuf);
    __syncthreads();

    for (int chunk = 0; chunk < NCHUNK; ++chunk) {
        const uint32_t abuf = abase + (uint32_t)(chunk & 1) * POOL_BUF;
        if (chunk + 1 < NCHUNK) POOL_LOAD((chunk + 1) * CH);

#pragma unroll
        for (int ks = 0; ks < 4; ++ks) {
            const uint32_t aOff = SWZ128((uint32_t)(aRow * 128 + ks * 32 + aColM));
            uint32_t ah[4], al[4];
            ldsm_x4(abuf + A_HI_OFF + aOff, ah);
            ldsm_x4(abuf + A_LO_OFF + aOff, al);
#pragma unroll
            for (int pp = 0; pp < 2; ++pp) {
                const uint32_t bOff =
                    SWZ128((uint32_t)((pp * 16 + bRow0) * 128 + ks * 32 + bColM));
                uint32_t bh[4], bl[4];
                ldsm_x4(abuf + B_HI_OFF + bOff, bh);   // NON-trans (K-major B)
                ldsm_x4(abuf + B_LO_OFF + bOff, bl);
                mma_bf16(acc[2 * pp],     ah, bh[0], bh[1]);
                mma_bf16(acc[2 * pp],     ah, bl[0], bl[1]);
                mma_bf16(acc[2 * pp],     al, bh[0], bh[1]);
                mma_bf16(acc[2 * pp + 1], ah, bh[2], bh[3]);
                mma_bf16(acc[2 * pp + 1], ah, bl[2], bl[3]);
                mma_bf16(acc[2 * pp + 1], al, bh[2], bh[3]);
            }
        }

        if (chunk + 1 < NCHUNK) POOL_STORE(sbuf + ((chunk + 1) & 1) * POOL_BUF);
        __syncthreads();
    }

    const float inv = 1.f / (float)HW;
    const int crow = c0 + rw + (lane >> 2);
#pragma unroll
    for (int p = 0; p < 4; ++p) {
        const int n = p * 8 + (lane & 3) * 2;
        g_fmraw[((size_t)b * Mm + n)     * Cc + crow]     = acc[p][0] * inv;
        g_fmraw[((size_t)b * Mm + n + 1) * Cc + crow]     = acc[p][1] * inv;
        g_fmraw[((size_t)b * Mm + n)     * Cc + crow + 8] = acc[p][2] * inv;
        g_fmraw[((size_t)b * Mm + n + 1) * Cc + crow + 8] = acc[p][3] * inv;
    }
#undef POOL_LOAD
#undef POOL_STORE
}

// ---------------------------------------------------------------------------
// Kernel C (fused): f = sign(x)*sqrt(|x|+eps); per-b L2 norm; writes
// NORMALIZED fm directly (k_norm eliminated — fc multiplies by constant 100).
// Also initializes p row b with the bias (k_p0 eliminated).
// ---------------------------------------------------------------------------
__global__ __launch_bounds__(1024) void k_ssqrt(
    float* __restrict__ out_fm, const float* __restrict__ fcb,
    float* __restrict__ out_p)
{
    const int b = blockIdx.x;
    float f[MC / 1024];                 // 24 values held in registers
    float ss = 0.f;
#pragma unroll
    for (int i = 0; i < MC / 1024; ++i) {
        float x = g_fmraw[b * MC + i * 1024 + threadIdx.x];
        float v = (x == 0.f) ? 0.f : copysignf(sqrtf(fabsf(x) + 1e-12f), x);
        f[i] = v;
        ss += v * v;
    }
    __shared__ float red[32];
    __shared__ float s_scale;
#pragma unroll
    for (int o = 16; o; o >>= 1) ss += __shfl_xor_sync(0xffffffffu, ss, o);
    if ((threadIdx.x & 31) == 0) red[threadIdx.x >> 5] = ss;
    __syncthreads();
    if (threadIdx.x < 32) {
        ss = red[threadIdx.x];
#pragma unroll
        for (int o = 16; o; o >>= 1) ss += __shfl_xor_sync(0xffffffffu, ss, o);
        if (threadIdx.x == 0)
            s_scale = 1.f / fmaxf(sqrtf(ss), 1e-12f);
    }
    __syncthreads();
    const float s = s_scale;
#pragma unroll
    for (int i = 0; i < MC / 1024; ++i)
        out_fm[b * MC + i * 1024 + threadIdx.x] = f[i] * s;

    if (threadIdx.x < NCLS)
        out_p[b * NCLS + threadIdx.x] = __ldg(&fcb[threadIdx.x]);
}

// ---------------------------------------------------------------------------
// Kernel D (mma.sync, split-k): p[b,n] += 100 * sum_k fm_norm[b,k] fcw[n,k]
// Grid (48 ksplit, 4 ntiles of 64). Per CTA: D[64b x 64n], K = 512 in 8
// chunks of 64. Warp w: m-tile wm=w&3 (16 b-rows), n-half wn=w>>2 (32 cols).
// Same fragment math as k_pool_mma (both operands K-major, non-trans ldsm).
// ---------------------------------------------------------------------------
#define FC_NSPLIT 48
#define FC_KS     (MC / FC_NSPLIT)      // 512
#define FC_NCH    (FC_KS / 64)          // 8
#define FA_HI 0
#define FA_LO 8192
#define FB_HI 16384
#define FB_LO 24576
#define FC_SMEM_DYN (32768 + 1024)

__global__ __launch_bounds__(256) void k_fc_mma(
    const float* __restrict__ fmn, const float* __restrict__ fcw,
    float* __restrict__ out_p)
{
    extern __shared__ char dyn_smem[];
    const int k0 = blockIdx.x * FC_KS;
    const int n0 = blockIdx.y * 64;
    const int t  = threadIdx.x;
    const int w  = t >> 5, lane = t & 31;
    const int wm = w & 3, wn = w >> 2;

    uint32_t raw = smem_u32(dyn_smem);
    uint32_t abase = (raw + 1023u) & ~1023u;
    char* sbuf = dyn_smem + (abase - raw);

    float acc[4][4];
#pragma unroll
    for (int p = 0; p < 4; ++p)
#pragma unroll
        for (int j = 0; j < 4; ++j) acc[p][j] = 0.f;

    const int r8   = lane & 7;
    const int aRow = wm * 16 + ((lane >> 3) & 1) * 8 + r8;
    const int aColM = ((lane >> 4) & 1) * 16;
    const int bRow0 = wn * 32 + ((lane >> 4) & 1) * 8 + r8;
    const int bColM = ((lane >> 3) & 1) * 16;

    for (int ch = 0; ch < FC_NCH; ++ch) {
        const int kc = k0 + ch * 64;
        __syncthreads();
        // stage A: fm_norm rows b 0..63, k chunk (SW128)
#pragma unroll
        for (int i = 0; i < 4; ++i) {
            int q = t + i * 256;        // 0..1023
            int row = q >> 4, qc = q & 15;
            float4 v = *(const float4*)(fmn + (size_t)row * MC + kc + qc * 4);
            uint32_t h01, l01, h23, l23;
            split_pack(v.x, v.y, h01, l01);
            split_pack(v.z, v.w, h23, l23);
            uint32_t off = SWZ128((uint32_t)(row * 128 + qc * 8));
            *(uint2*)(sbuf + FA_HI + off) = make_uint2(h01, h23);
            *(uint2*)(sbuf + FA_LO + off) = make_uint2(l01, l23);
        }
        // stage B: fcw rows n0..n0+63 (zero-pad n>=200), k chunk (SW128)
#pragma unroll
        for (int i = 0; i < 4; ++i) {
            int q = t + i * 256;
            int row = q >> 4, qc = q & 15;
            int n = n0 + row;
            float4 v = (n < NCLS)
                ? *(const float4*)(fcw + (size_t)n * MC + kc + qc * 4)
                : make_float4(0.f, 0.f, 0.f, 0.f);
            uint32_t h01, l01, h23, l23;
            split_pack(v.x, v.y, h01, l01);
            split_pack(v.z, v.w, h23, l23);
            uint32_t off = SWZ128((uint32_t)(row * 128 + qc * 8));
            *(uint2*)(sbuf + FB_HI + off) = make_uint2(h01, h23);
            *(uint2*)(sbuf + FB_LO + off) = make_uint2(l01, l23);
        }
        __syncthreads();

#pragma unroll
        for (int ks = 0; ks < 4; ++ks) {
            const uint32_t aOff = SWZ128((uint32_t)(aRow * 128 + ks * 32 + aColM));
            uint32_t ah[4], al[4];
            ldsm_x4(abase + FA_HI + aOff, ah);
            ldsm_x4(abase + FA_LO + aOff, al);
#pragma unroll
            for (int pp = 0; pp < 2; ++pp) {
                const uint32_t bOff =
                    SWZ128((uint32_t)((bRow0 + pp * 16) * 128 + ks * 32 + bColM));
                uint32_t bh[4], bl[4];
                ldsm_x4(abase + FB_HI + bOff, bh);
                ldsm_x4(abase + FB_LO + bOff, bl);
                mma_bf16(acc[2 * pp],     ah, bh[0], bh[1]);
                mma_bf16(acc[2 * pp],     ah, bl[0], bl[1]);
                mma_bf16(acc[2 * pp],     al, bh[0], bh[1]);
                mma_bf16(acc[2 * pp + 1], ah, bh[2], bh[3]);
                mma_bf16(acc[2 * pp + 1], ah, bl[2], bl[3]);
                mma_bf16(acc[2 * pp + 1], al, bh[2], bh[3]);
            }
        }
    }

    // epilogue: p[b, n] += acc * 100 (bias pre-written by k_ssqrt)
    const int brow = wm * 16 + (lane >> 2);
#pragma unroll
    for (int p = 0; p < 4; ++p) {
        const int n = n0 + wn * 32 + p * 8 + (lane & 3) * 2;
        if (n < NCLS) {
            atomicAdd(&out_p[brow * NCLS + n],       acc[p][0] * 100.f);
            atomicAdd(&out_p[(brow + 8) * NCLS + n], acc[p][2] * 100.f);
        }
        if (n + 1 < NCLS) {
            atomicAdd(&out_p[brow * NCLS + n + 1],       acc[p][1] * 100.f);
            atomicAdd(&out_p[(brow + 8) * NCLS + n + 1], acc[p][3] * 100.f);
        }
    }
}

// ---------------------------------------------------------------------------
extern "C" void kernel_launch(void* const* d_in, const int* in_sizes, int n_in,
                              void* d_out, int out_size)
{
    const float* fmap = (const float*)d_in[0];
    const float* attw = (const float*)d_in[1];
    const float* attb = (const float*)d_in[2];
    const float* fcw  = (const float*)d_in[3];
    const float* fcb  = (const float*)d_in[4];
    float* out     = (float*)d_out;
    float* out_p   = out + OFF_P;
    float* out_fm  = out + OFF_FM;
    float* out_att = out + OFF_ATT;
    (void)in_sizes; (void)n_in; (void)out_size;

    // >48KB dynamic smem opt-in (attribute set, not an allocation; idempotent)
    cudaFuncSetAttribute(k_att_mma,  cudaFuncAttributeMaxDynamicSharedMemorySize,
                         ATT_SMEM_DYN);
    cudaFuncSetAttribute(k_pool_mma, cudaFuncAttributeMaxDynamicSharedMemorySize,
                         POOL_SMEM_DYN);

    // 4 launches; ncu capture slot (idx 3) = k_fc_mma this round.
    k_att_mma <<<dim3(6, 64), 256, ATT_SMEM_DYN>>>(fmap, attw, attb, out_att);
    k_pool_mma<<<dim3(6, 64), 256, POOL_SMEM_DYN>>>(fmap, out_att);
    k_ssqrt   <<<Bn, 1024>>>(out_fm, fcb, out_p);
    k_fc_mma  <<<dim3(FC_NSPLIT, 4), 256, FC_SMEM_DYN>>>(out_fm, fcw, out_p);
}

// round 13
// speedup vs baseline: 4.7544x; 1.0474x over previous
#include <cuda_runtime.h>
#include <cuda_bf16.h>
#include <cstdint>

// Problem constants
#define Bn   64
#define Cc   768
#define HW   676          // 26*26
#define Mm   32
#define NCLS 200
#define MC   (Mm*Cc)      // 24576
#define OFF_P   0
#define OFF_FM  (Bn*NCLS)                  // 12800
#define OFF_ATT (OFF_FM + Bn*MC)           // 12800 + 1572864

// Scratch (device-code use only; never passed from host).
__device__ float g_ss[Bn];             // per-batch sum of f^2 (atomic)
__device__ float g_scale[Bn];          // 1/max(||f||,eps)
__device__ float g_scale100[Bn];       // 100/max(||f||,eps)

// ===========================================================================
// Baseline-ISA tensor helpers (ldmatrix + mma.sync assemble for plain sm_103;
// tcgen05 does NOT — harness assembles a non-'a' target).
// ===========================================================================
__device__ __forceinline__ uint32_t smem_u32(const void* p) {
    uint32_t r;
    asm("{ .reg .u64 t; cvta.to.shared.u64 t, %1; cvt.u32.u64 %0, t; }"
        : "=r"(r) : "l"(p));
    return r;
}
#define SWZ128(o)  ((o) ^ (((o) >> 3) & 0x70))

__device__ __forceinline__ void ldsm_x4(uint32_t addr, uint32_t r[4]) {
    asm volatile("ldmatrix.sync.aligned.m8n8.x4.shared.b16 {%0,%1,%2,%3}, [%4];"
                 : "=r"(r[0]), "=r"(r[1]), "=r"(r[2]), "=r"(r[3]) : "r"(addr));
}
__device__ __forceinline__ void ldsm_x4_t(uint32_t addr, uint32_t r[4]) {
    asm volatile("ldmatrix.sync.aligned.m8n8.x4.trans.shared.b16 {%0,%1,%2,%3}, [%4];"
                 : "=r"(r[0]), "=r"(r[1]), "=r"(r[2]), "=r"(r[3]) : "r"(addr));
}
__device__ __forceinline__ void mma_bf16(float* c, const uint32_t a[4],
                                         uint32_t b0, uint32_t b1) {
    asm volatile(
        "mma.sync.aligned.m16n8k16.row.col.f32.bf16.bf16.f32 "
        "{%0,%1,%2,%3}, {%4,%5,%6,%7}, {%8,%9}, {%0,%1,%2,%3};"
        : "+f"(c[0]), "+f"(c[1]), "+f"(c[2]), "+f"(c[3])
        : "r"(a[0]), "r"(a[1]), "r"(a[2]), "r"(a[3]), "r"(b0), "r"(b1));
}

// hi/lo bf16 split of a float pair (exact residual; minimal issue count)
__device__ __forceinline__ void split_pack(float x, float y,
                                           uint32_t& hi, uint32_t& lo) {
    __nv_bfloat162 h2 = __floats2bfloat162_rn(x, y);    // x -> low half
    uint32_t h = *(uint32_t*)&h2;
    float hx = __uint_as_float(h << 16);
    float hy = __uint_as_float(h & 0xFFFF0000u);
    __nv_bfloat162 l2 = __floats2bfloat162_rn(x - hx, y - hy);
    hi = h;
    lo = *(uint32_t*)&l2;
}

// ---------------------------------------------------------------------------
// Kernel A (mma.sync, double-buffered): att = relu(W @ X + bias)
// Per CTA (hw-tile 128, batch b): D[32m x 128hw], K = c in 12 chunks of 64.
// Also zeroes g_ss[b] (att completes before pool starts).
// ---------------------------------------------------------------------------
#define KCH      64
#define NKCH     12
#define PXB      272                    // X row pitch bytes (136 bf16)
#define X_HI_OFF 0                      // 64*272 = 17408
#define X_LO_OFF 17408
#define W_HI_OFF 34816                  // 34*1024 (SW128 region 1024-aligned)
#define W_LO_OFF 38912
#define ATT_BUF  43008                  // 42*1024
#define ATT_SMEM_DYN (2 * ATT_BUF + 1024)

__global__ __launch_bounds__(256, 2) void k_att_mma(
    const float* __restrict__ fmap, const float* __restrict__ attw,
    const float* __restrict__ attb, float* __restrict__ out_att)
{
    extern __shared__ char dyn_smem[];
    const int b   = blockIdx.y;
    const int hwt = blockIdx.x * 128;
    const int t   = threadIdx.x;
    const int w   = t >> 5, lane = t & 31;

    if (blockIdx.x == 0 && t == 0) g_ss[b] = 0.f;   // pre-zero for pool atomics

    uint32_t raw = smem_u32(dyn_smem);
    uint32_t abase = (raw + 1023u) & ~1023u;
    char* sbuf = dyn_smem + (abase - raw);

    const float* X = fmap + (size_t)b * Cc * HW;

    float acc[2][2][4];
#pragma unroll
    for (int mt = 0; mt < 2; ++mt)
#pragma unroll
        for (int nt = 0; nt < 2; ++nt)
#pragma unroll
            for (int j = 0; j < 4; ++j) acc[mt][nt][j] = 0.f;

    const int r8 = lane & 7;
    const int aRowIn = ((lane >> 3) & 1) * 8 + r8;
    const int aColB  = ((lane >> 4) & 1) * 16;
    const int bKrow  = lane & 15;
    const int bNcol  = w * 16 + ((lane >> 4) & 1) * 8;

    float4 xv[8], wv[2];
    const int xrow[8] = { (t) >> 5, (t + 256) >> 5, (t + 512) >> 5, (t + 768) >> 5,
                          (t + 1024) >> 5, (t + 1280) >> 5, (t + 1536) >> 5, (t + 1792) >> 5 };
    const int xqc  = t & 31;
    const int xhw  = hwt + xqc * 4;
    const bool xok = xhw < HW;          // HW%4==0 -> whole quad in range
    const int wrow[2] = { t >> 4, (t + 256) >> 4 };
    const int wqc  = t & 15;

#define ATT_LOAD(c0_)                                                         \
    do {                                                                      \
        _Pragma("unroll")                                                     \
        for (int i = 0; i < 8; ++i)                                           \
            xv[i] = xok ? *(const float4*)(X + (size_t)((c0_) + xrow[i]) * HW + xhw) \
                        : make_float4(0.f, 0.f, 0.f, 0.f);                    \
        _Pragma("unroll")                                                     \
        for (int i = 0; i < 2; ++i)                                           \
            wv[i] = *(const float4*)(attw + (size_t)wrow[i] * Cc + (c0_) + wqc * 4); \
    } while (0)

#define ATT_STORE(dst_)                                                       \
    do {                                                                      \
        char* db_ = (dst_);                                                   \
        _Pragma("unroll")                                                     \
        for (int i = 0; i < 8; ++i) {                                         \
            uint32_t h01, l01, h23, l23;                                      \
            split_pack(xv[i].x, xv[i].y, h01, l01);                           \
            split_pack(xv[i].z, xv[i].w, h23, l23);                           \
            uint32_t off = (uint32_t)(xrow[i] * PXB + xqc * 8);               \
            *(uint2*)(db_ + X_HI_OFF + off) = make_uint2(h01, h23);           \
            *(uint2*)(db_ + X_LO_OFF + off) = make_uint2(l01, l23);           \
        }                                                                     \
        _Pragma("unroll")                                                     \
        for (int i = 0; i < 2; ++i) {                                         \
            uint32_t h01, l01, h23, l23;                                      \
            split_pack(wv[i].x, wv[i].y, h01, l01);                           \
            split_pack(wv[i].z, wv[i].w, h23, l23);                           \
            uint32_t off = SWZ128((uint32_t)(wrow[i] * 128 + wqc * 8));       \
            *(uint2*)(db_ + W_HI_OFF + off) = make_uint2(h01, h23);           \
            *(uint2*)(db_ + W_LO_OFF + off) = make_uint2(l01, l23);           \
        }                                                                     \
    } while (0)

    ATT_LOAD(0);
    ATT_STORE(sbuf);
    __syncthreads();

    for (int ch = 0; ch < NKCH; ++ch) {
        const uint32_t abuf = abase + (uint32_t)(ch & 1) * ATT_BUF;
        if (ch + 1 < NKCH) ATT_LOAD((ch + 1) * KCH);   // LDG in flight over mma

#pragma unroll
        for (int ks = 0; ks < 4; ++ks) {
            uint32_t ah[2][4], al[2][4];
#pragma unroll
            for (int mt = 0; mt < 2; ++mt) {
                uint32_t aOff = SWZ128((uint32_t)((mt * 16 + aRowIn) * 128 +
                                                  ks * 32 + aColB));
                ldsm_x4(abuf + W_HI_OFF + aOff, ah[mt]);
                ldsm_x4(abuf + W_LO_OFF + aOff, al[mt]);
            }
            uint32_t bOff = (uint32_t)((ks * 16 + bKrow) * PXB + bNcol * 2);
            uint32_t bh[4], bl[4];
            ldsm_x4_t(abuf + X_HI_OFF + bOff, bh);
            ldsm_x4_t(abuf + X_LO_OFF + bOff, bl);
#pragma unroll
            for (int mt = 0; mt < 2; ++mt)
#pragma unroll
                for (int nt = 0; nt < 2; ++nt) {
                    mma_bf16(acc[mt][nt], ah[mt], bh[2 * nt], bh[2 * nt + 1]);
                    mma_bf16(acc[mt][nt], ah[mt], bl[2 * nt], bl[2 * nt + 1]);
                    mma_bf16(acc[mt][nt], al[mt], bh[2 * nt], bh[2 * nt + 1]);
                }
        }

        if (ch + 1 < NKCH) ATT_STORE(sbuf + ((ch + 1) & 1) * ATT_BUF);
        __syncthreads();
    }

    float* ob = out_att + (size_t)b * Mm * HW;
#pragma unroll
    for (int mt = 0; mt < 2; ++mt) {
        const int m  = mt * 16 + (lane >> 2);
        const float bs0 = __ldg(&attb[m]);
        const float bs8 = __ldg(&attb[m + 8]);
#pragma unroll
        for (int nt = 0; nt < 2; ++nt) {
            int hwc = hwt + w * 16 + nt * 8 + 2 * (lane & 3);
            if (hwc + 1 < HW) {
                ob[(size_t)m * HW + hwc]           = fmaxf(acc[mt][nt][0] + bs0, 0.f);
                ob[(size_t)m * HW + hwc + 1]       = fmaxf(acc[mt][nt][1] + bs0, 0.f);
                ob[(size_t)(m + 8) * HW + hwc]     = fmaxf(acc[mt][nt][2] + bs8, 0.f);
                ob[(size_t)(m + 8) * HW + hwc + 1] = fmaxf(acc[mt][nt][3] + bs8, 0.f);
            }
        }
    }
#undef ATT_LOAD
#undef ATT_STORE
}

// ---------------------------------------------------------------------------
// Kernel B (mma.sync, double-buffered): pool + fused sign-sqrt epilogue.
// D[128c x 32m] = (1/676) fm @ att^T; then f = sign(v)*sqrt(|v|+eps) written
// UNNORMALIZED to out_fm; block partial sum(f^2) atomicAdd'ed to g_ss[b].
// ---------------------------------------------------------------------------
#define CH       64
#define NCHUNK   11
#define A_HI_OFF 0
#define A_LO_OFF 16384
#define B_HI_OFF 32768
#define B_LO_OFF 36864
#define POOL_BUF 40960                  // 40*1024
#define POOL_SMEM_DYN (2 * POOL_BUF + 1024)

__global__ __launch_bounds__(256, 2) void k_pool_mma(
    const float* __restrict__ fmap, const float* __restrict__ att,
    float* __restrict__ out_fm)
{
    extern __shared__ char dyn_smem[];

    const int b  = blockIdx.y;
    const int c0 = blockIdx.x * 128;
    const int t  = threadIdx.x;
    const int w  = t >> 5, lane = t & 31;
    const int rw = w * 16;

    uint32_t raw = smem_u32(dyn_smem);
    uint32_t abase = (raw + 1023u) & ~1023u;
    char* sbuf = dyn_smem + (abase - raw);

    const float* Aruns = fmap + (size_t)(b * Cc + c0) * HW;
    const float* Bruns = att  + (size_t)b * Mm * HW;

    float acc[4][4];
#pragma unroll
    for (int p = 0; p < 4; ++p)
#pragma unroll
        for (int j = 0; j < 4; ++j) acc[p][j] = 0.f;

    const int r8   = lane & 7;
    const int aRow = rw + ((lane >> 3) & 1) * 8 + r8;
    const int aColM = ((lane >> 4) & 1) * 16;
    const int bRow0 = ((lane >> 4) & 1) * 8 + r8;
    const int bColM = ((lane >> 3) & 1) * 16;

    float4 av[8], bv[2];
    const int arow[8] = { (t) >> 4, (t + 256) >> 4, (t + 512) >> 4, (t + 768) >> 4,
                          (t + 1024) >> 4, (t + 1280) >> 4, (t + 1536) >> 4, (t + 1792) >> 4 };
    const int aqc = t & 15;

#define POOL_LOAD(hw0_)                                                       \
    do {                                                                      \
        const int hwq_ = (hw0_) + aqc * 4;                                    \
        const bool ok_ = hwq_ + 3 < HW;                                       \
        _Pragma("unroll")                                                     \
        for (int i = 0; i < 8; ++i)                                           \
            av[i] = ok_ ? *(const float4*)(Aruns + (size_t)arow[i] * HW + hwq_) \
                        : make_float4(0.f, 0.f, 0.f, 0.f);                    \
        _Pragma("unroll")                                                     \
        for (int i = 0; i < 2; ++i) {                                         \
            int row_ = (t + i * 256) >> 4;                                    \
            bv[i] = ok_ ? *(const float4*)(Bruns + (size_t)row_ * HW + hwq_)  \
                        : make_float4(0.f, 0.f, 0.f, 0.f);                    \
        }                                                                     \
    } while (0)

#define POOL_STORE(dst_)                                                      \
    do {                                                                      \
        char* db_ = (dst_);                                                   \
        _Pragma("unroll")                                                     \
        for (int i = 0; i < 8; ++i) {                                         \
            uint32_t h01, l01, h23, l23;                                      \
            split_pack(av[i].x, av[i].y, h01, l01);                           \
            split_pack(av[i].z, av[i].w, h23, l23);                           \
            uint32_t off = SWZ128((uint32_t)(arow[i] * 128 + aqc * 8));       \
            *(uint2*)(db_ + A_HI_OFF + off) = make_uint2(h01, h23);           \
            *(uint2*)(db_ + A_LO_OFF + off) = make_uint2(l01, l23);           \
        }                                                                     \
        _Pragma("unroll")                                                     \
        for (int i = 0; i < 2; ++i) {                                         \
            int row_ = (t + i * 256) >> 4;                                    \
            uint32_t h01, l01, h23, l23;                                      \
            split_pack(bv[i].x, bv[i].y, h01, l01);                           \
            split_pack(bv[i].z, bv[i].w, h23, l23);                           \
            uint32_t off = SWZ128((uint32_t)(row_ * 128 + aqc * 8));          \
            *(uint2*)(db_ + B_HI_OFF + off) = make_uint2(h01, h23);           \
            *(uint2*)(db_ + B_LO_OFF + off) = make_uint2(l01, l23);           \
        }                                                                     \
    } while (0)

    POOL_LOAD(0);
    POOL_STORE(sbuf);
    __syncthreads();

    for (int chunk = 0; chunk < NCHUNK; ++chunk) {
        const uint32_t abuf = abase + (uint32_t)(chunk & 1) * POOL_BUF;
        if (chunk + 1 < NCHUNK) POOL_LOAD((chunk + 1) * CH);

#pragma unroll
        for (int ks = 0; ks < 4; ++ks) {
            const uint32_t aOff = SWZ128((uint32_t)(aRow * 128 + ks * 32 + aColM));
            uint32_t ah[4], al[4];
            ldsm_x4(abuf + A_HI_OFF + aOff, ah);
            ldsm_x4(abuf + A_LO_OFF + aOff, al);
#pragma unroll
            for (int pp = 0; pp < 2; ++pp) {
                const uint32_t bOff =
                    SWZ128((uint32_t)((pp * 16 + bRow0) * 128 + ks * 32 + bColM));
                uint32_t bh[4], bl[4];
                ldsm_x4(abuf + B_HI_OFF + bOff, bh);   // NON-trans (K-major B)
                ldsm_x4(abuf + B_LO_OFF + bOff, bl);
                mma_bf16(acc[2 * pp],     ah, bh[0], bh[1]);
                mma_bf16(acc[2 * pp],     ah, bl[0], bl[1]);
                mma_bf16(acc[2 * pp],     al, bh[0], bh[1]);
                mma_bf16(acc[2 * pp + 1], ah, bh[2], bh[3]);
                mma_bf16(acc[2 * pp + 1], ah, bl[2], bl[3]);
                mma_bf16(acc[2 * pp + 1], al, bh[2], bh[3]);
            }
        }

        if (chunk + 1 < NCHUNK) POOL_STORE(sbuf + ((chunk + 1) & 1) * POOL_BUF);
        __syncthreads();
    }

    // ---- fused epilogue: sign-sqrt, write unnormalized f, reduce sum(f^2) ----
    const float inv = 1.f / (float)HW;
    const int crow = c0 + rw + (lane >> 2);
    float ssq = 0.f;
#pragma unroll
    for (int p = 0; p < 4; ++p) {
        const int n = p * 8 + (lane & 3) * 2;
#pragma unroll
        for (int j = 0; j < 4; ++j) {
            float x = acc[p][j] * inv;
            float f = (x == 0.f) ? 0.f : copysignf(sqrtf(fabsf(x) + 1e-12f), x);
            acc[p][j] = f;
            ssq += f * f;
        }
        out_fm[((size_t)b * Mm + n)     * Cc + crow]     = acc[p][0];
        out_fm[((size_t)b * Mm + n + 1) * Cc + crow]     = acc[p][1];
        out_fm[((size_t)b * Mm + n)     * Cc + crow + 8] = acc[p][2];
        out_fm[((size_t)b * Mm + n + 1) * Cc + crow + 8] = acc[p][3];
    }
    __shared__ float red[8];
#pragma unroll
    for (int o = 16; o; o >>= 1) ssq += __shfl_xor_sync(0xffffffffu, ssq, o);
    if (lane == 0) red[w] = ssq;
    __syncthreads();
    if (t < 8) {
        float s = red[t];
#pragma unroll
        for (int o = 4; o; o >>= 1) s += __shfl_xor_sync(0xffu, s, o);
        if (t == 0) atomicAdd(&g_ss[b], s);
    }
#undef POOL_LOAD
#undef POOL_STORE
}

// ---------------------------------------------------------------------------
// Kernel C: scales from g_ss; p initialized with bias.
// ---------------------------------------------------------------------------
__global__ __launch_bounds__(256) void k_scale(
    const float* __restrict__ fcb, float* __restrict__ out_p)
{
    if (blockIdx.x == 0 && threadIdx.x < Bn) {
        float s = 1.f / fmaxf(sqrtf(g_ss[threadIdx.x]), 1e-12f);
        g_scale[threadIdx.x] = s;
        g_scale100[threadIdx.x] = 100.f * s;
    }
    int i = blockIdx.x * 256 + threadIdx.x;
    if (i < Bn * NCLS) out_p[i] = __ldg(&fcb[i % NCLS]);
}

// ---------------------------------------------------------------------------
// Kernel D (mma.sync, double-buffered, split-k):
// p[b,n] += sum_k (f_unnorm[b,k] * g_scale100[b]) * fcw[n,k]
// Grid (48 ksplit, 4 ntiles of 64). Per CTA: D[64b x 64n], 8 chunks of 64.
// ---------------------------------------------------------------------------
#define FC_NSPLIT 48
#define FC_KS     (MC / FC_NSPLIT)      // 512
#define FC_NCH    (FC_KS / 64)          // 8
#define FA_HI 0
#define FA_LO 8192
#define FB_HI 16384
#define FB_LO 24576
#define FC_BUF 32768
#define FC_SMEM_DYN (2 * FC_BUF + 1024)

__global__ __launch_bounds__(256, 2) void k_fc_mma(
    const float* __restrict__ fmn, const float* __restrict__ fcw,
    float* __restrict__ out_p)
{
    extern __shared__ char dyn_smem[];
    const int k0 = blockIdx.x * FC_KS;
    const int n0 = blockIdx.y * 64;
    const int t  = threadIdx.x;
    const int w  = t >> 5, lane = t & 31;
    const int wm = w & 3, wn = w >> 2;

    uint32_t raw = smem_u32(dyn_smem);
    uint32_t abase = (raw + 1023u) & ~1023u;
    char* sbuf = dyn_smem + (abase - raw);

    float acc[4][4];
#pragma unroll
    for (int p = 0; p < 4; ++p)
#pragma unroll
        for (int j = 0; j < 4; ++j) acc[p][j] = 0.f;

    const int r8   = lane & 7;
    const int aRow = wm * 16 + ((lane >> 3) & 1) * 8 + r8;
    const int aColM = ((lane >> 4) & 1) * 16;
    const int bRow0 = wn * 32 + ((lane >> 4) & 1) * 8 + r8;
    const int bColM = ((lane >> 3) & 1) * 16;

    // staging coords
    const int srow = t >> 4, sqc = t & 15;        // +64 rows per i-step of 4
    float4 avv[4], bvv[4];
    float sA[4];
#pragma unroll
    for (int i = 0; i < 4; ++i)
        sA[i] = g_scale100[(srow + i * 16) & 63];

#define FC_LOAD(kc_)                                                          \
    do {                                                                      \
        _Pragma("unroll")                                                     \
        for (int i = 0; i < 4; ++i) {                                         \
            int row = srow + i * 16;                                          \
            float4 v = *(const float4*)(fmn + (size_t)row * MC + (kc_) + sqc * 4); \
            v.x *= sA[i]; v.y *= sA[i]; v.z *= sA[i]; v.w *= sA[i];           \
            avv[i] = v;                                                       \
            int n = n0 + row;                                                 \
            bvv[i] = (n < NCLS)                                               \
                ? *(const float4*)(fcw + (size_t)n * MC + (kc_) + sqc * 4)    \
                : make_float4(0.f, 0.f, 0.f, 0.f);                            \
        }                                                                     \
    } while (0)

#define FC_STORE(dst_)                                                        \
    do {                                                                      \
        char* db_ = (dst_);                                                   \
        _Pragma("unroll")                                                     \
        for (int i = 0; i < 4; ++i) {                                         \
            int row = srow + i * 16;                                          \
            uint32_t off = SWZ128((uint32_t)(row * 128 + sqc * 8));           \
            uint32_t h01, l01, h23, l23;                                      \
            split_pack(avv[i].x, avv[i].y, h01, l01);                         \
            split_pack(avv[i].z, avv[i].w, h23, l23);                         \
            *(uint2*)(db_ + FA_HI + off) = make_uint2(h01, h23);              \
            *(uint2*)(db_ + FA_LO + off) = make_uint2(l01, l23);              \
            split_pack(bvv[i].x, bvv[i].y, h01, l01);                         \
            split_pack(bvv[i].z, bvv[i].w, h23, l23);                         \
            *(uint2*)(db_ + FB_HI + off) = make_uint2(h01, h23);              \
            *(uint2*)(db_ + FB_LO + off) = make_uint2(l01, l23);              \
        }                                                                     \
    } while (0)

    FC_LOAD(k0);
    FC_STORE(sbuf);
    __syncthreads();

    for (int ch = 0; ch < FC_NCH; ++ch) {
        const uint32_t abuf = abase + (uint32_t)(ch & 1) * FC_BUF;
        if (ch + 1 < FC_NCH) FC_LOAD(k0 + (ch + 1) * 64);

#pragma unroll
        for (int ks = 0; ks < 4; ++ks) {
            const uint32_t aOff = SWZ128((uint32_t)(aRow * 128 + ks * 32 + aColM));
            uint32_t ah[4], al[4];
            ldsm_x4(abuf + FA_HI + aOff, ah);
            ldsm_x4(abuf + FA_LO + aOff, al);
#pragma unroll
            for (int pp = 0; pp < 2; ++pp) {
                const uint32_t bOff =
                    SWZ128((uint32_t)((bRow0 + pp * 16) * 128 + ks * 32 + bColM));
                uint32_t bh[4], bl[4];
                ldsm_x4(abuf + FB_HI + bOff, bh);
                ldsm_x4(abuf + FB_LO + bOff, bl);
                mma_bf16(acc[2 * pp],     ah, bh[0], bh[1]);
                mma_bf16(acc[2 * pp],     ah, bl[0], bl[1]);
                mma_bf16(acc[2 * pp],     al, bh[0], bh[1]);
                mma_bf16(acc[2 * pp + 1], ah, bh[2], bh[3]);
                mma_bf16(acc[2 * pp + 1], ah, bl[2], bl[3]);
                mma_bf16(acc[2 * pp + 1], al, bh[2], bh[3]);
            }
        }

        if (ch + 1 < FC_NCH) FC_STORE(sbuf + ((ch + 1) & 1) * FC_BUF);
        __syncthreads();
    }

    // epilogue: p[b, n] += acc (scale folded into A staging; bias pre-written)
    const int brow = wm * 16 + (lane >> 2);
#pragma unroll
    for (int p = 0; p < 4; ++p) {
        const int n = n0 + wn * 32 + p * 8 + (lane & 3) * 2;
        if (n < NCLS) {
            atomicAdd(&out_p[brow * NCLS + n],       acc[p][0]);
            atomicAdd(&out_p[(brow + 8) * NCLS + n], acc[p][2]);
        }
        if (n + 1 < NCLS) {
            atomicAdd(&out_p[brow * NCLS + n + 1],       acc[p][1]);
            atomicAdd(&out_p[(brow + 8) * NCLS + n + 1], acc[p][3]);
        }
    }
#undef FC_LOAD
#undef FC_STORE
}

// ---------------------------------------------------------------------------
// Kernel E: normalize fm in place (after fc consumed unnormalized values)
// ---------------------------------------------------------------------------
__global__ __launch_bounds__(256) void k_norm(float* __restrict__ out_fm)
{
    const int b = blockIdx.y;
    const int i = blockIdx.x * 256 + threadIdx.x;   // 96*256 = MC exactly
    out_fm[(size_t)b * MC + i] *= g_scale[b];
}

// ---------------------------------------------------------------------------
extern "C" void kernel_launch(void* const* d_in, const int* in_sizes, int n_in,
                              void* d_out, int out_size)
{
    const float* fmap = (const float*)d_in[0];
    const float* attw = (const float*)d_in[1];
    const float* attb = (const float*)d_in[2];
    const float* fcw  = (const float*)d_in[3];
    const float* fcb  = (const float*)d_in[4];
    float* out     = (float*)d_out;
    float* out_p   = out + OFF_P;
    float* out_fm  = out + OFF_FM;
    float* out_att = out + OFF_ATT;
    (void)in_sizes; (void)n_in; (void)out_size;

    // >48KB dynamic smem opt-in (attribute set, not an allocation; idempotent)
    cudaFuncSetAttribute(k_att_mma,  cudaFuncAttributeMaxDynamicSharedMemorySize,
                         ATT_SMEM_DYN);
    cudaFuncSetAttribute(k_pool_mma, cudaFuncAttributeMaxDynamicSharedMemorySize,
                         POOL_SMEM_DYN);
    cudaFuncSetAttribute(k_fc_mma,   cudaFuncAttributeMaxDynamicSharedMemorySize,
                         FC_SMEM_DYN);

    // 5 launches; ncu capture slot (idx 3) = k_fc_mma (verifying double-buffer).
    k_att_mma <<<dim3(6, 64), 256, ATT_SMEM_DYN>>>(fmap, attw, attb, out_att);
    k_pool_mma<<<dim3(6, 64), 256, POOL_SMEM_DYN>>>(fmap, out_att, out_fm);
    k_scale   <<<50, 256>>>(fcb, out_p);
    k_fc_mma  <<<dim3(FC_NSPLIT, 4), 256, FC_SMEM_DYN>>>(out_fm, fcw, out_p);
    k_norm    <<<dim3(96, 64), 256>>>(out_fm);
}

// round 14
// speedup vs baseline: 4.8104x; 1.0118x over previous
#include <cuda_runtime.h>
#include <cuda_bf16.h>
#include <cstdint>

// Problem constants
#define Bn   64
#define Cc   768
#define HW   676          // 26*26
#define Mm   32
#define NCLS 200
#define MC   (Mm*Cc)      // 24576
#define OFF_P   0
#define OFF_FM  (Bn*NCLS)                  // 12800
#define OFF_ATT (OFF_FM + Bn*MC)           // 12800 + 1572864

// Scratch (device-code use only; never passed from host).
__device__ float g_ss[Bn];             // per-batch sum of f^2 (atomic)
__device__ float g_scale[Bn];          // 1/max(||f||,eps)
__device__ float g_scale100[Bn];       // 100/max(||f||,eps)

// ===========================================================================
// Baseline-ISA tensor helpers (ldmatrix + mma.sync assemble for plain sm_103;
// tcgen05 does NOT — harness assembles a non-'a' target).
// ===========================================================================
__device__ __forceinline__ uint32_t smem_u32(const void* p) {
    uint32_t r;
    asm("{ .reg .u64 t; cvta.to.shared.u64 t, %1; cvt.u32.u64 %0, t; }"
        : "=r"(r) : "l"(p));
    return r;
}
#define SWZ128(o)  ((o) ^ (((o) >> 3) & 0x70))

__device__ __forceinline__ void ldsm_x4(uint32_t addr, uint32_t r[4]) {
    asm volatile("ldmatrix.sync.aligned.m8n8.x4.shared.b16 {%0,%1,%2,%3}, [%4];"
                 : "=r"(r[0]), "=r"(r[1]), "=r"(r[2]), "=r"(r[3]) : "r"(addr));
}
__device__ __forceinline__ void ldsm_x4_t(uint32_t addr, uint32_t r[4]) {
    asm volatile("ldmatrix.sync.aligned.m8n8.x4.trans.shared.b16 {%0,%1,%2,%3}, [%4];"
                 : "=r"(r[0]), "=r"(r[1]), "=r"(r[2]), "=r"(r[3]) : "r"(addr));
}
__device__ __forceinline__ void mma_bf16(float* c, const uint32_t a[4],
                                         uint32_t b0, uint32_t b1) {
    asm volatile(
        "mma.sync.aligned.m16n8k16.row.col.f32.bf16.bf16.f32 "
        "{%0,%1,%2,%3}, {%4,%5,%6,%7}, {%8,%9}, {%0,%1,%2,%3};"
        : "+f"(c[0]), "+f"(c[1]), "+f"(c[2]), "+f"(c[3])
        : "r"(a[0]), "r"(a[1]), "r"(a[2]), "r"(a[3]), "r"(b0), "r"(b1));
}

// hi/lo bf16 split of a float pair (exact residual; minimal issue count)
__device__ __forceinline__ void split_pack(float x, float y,
                                           uint32_t& hi, uint32_t& lo) {
    __nv_bfloat162 h2 = __floats2bfloat162_rn(x, y);    // x -> low half
    uint32_t h = *(uint32_t*)&h2;
    float hx = __uint_as_float(h << 16);
    float hy = __uint_as_float(h & 0xFFFF0000u);
    __nv_bfloat162 l2 = __floats2bfloat162_rn(x - hx, y - hy);
    hi = h;
    lo = *(uint32_t*)&l2;
}

// ---------------------------------------------------------------------------
// Kernel A (mma.sync, double-buffered): att = relu(W @ X + bias)
// Per CTA (hw-tile 128, batch b): D[32m x 128hw], K = c in 12 chunks of 64.
// Also zeroes g_ss[b] (att completes before pool starts).
// ---------------------------------------------------------------------------
#define KCH      64
#define NKCH     12
#define PXB      272                    // X row pitch bytes (136 bf16)
#define X_HI_OFF 0                      // 64*272 = 17408
#define X_LO_OFF 17408
#define W_HI_OFF 34816                  // 34*1024 (SW128 region 1024-aligned)
#define W_LO_OFF 38912
#define ATT_BUF  43008                  // 42*1024
#define ATT_SMEM_DYN (2 * ATT_BUF + 1024)

__global__ __launch_bounds__(256, 2) void k_att_mma(
    const float* __restrict__ fmap, const float* __restrict__ attw,
    const float* __restrict__ attb, float* __restrict__ out_att)
{
    extern __shared__ char dyn_smem[];
    const int b   = blockIdx.y;
    const int hwt = blockIdx.x * 128;
    const int t   = threadIdx.x;
    const int w   = t >> 5, lane = t & 31;

    if (blockIdx.x == 0 && t == 0) g_ss[b] = 0.f;   // pre-zero for pool atomics

    uint32_t raw = smem_u32(dyn_smem);
    uint32_t abase = (raw + 1023u) & ~1023u;
    char* sbuf = dyn_smem + (abase - raw);

    const float* X = fmap + (size_t)b * Cc * HW;

    float acc[2][2][4];
#pragma unroll
    for (int mt = 0; mt < 2; ++mt)
#pragma unroll
        for (int nt = 0; nt < 2; ++nt)
#pragma unroll
            for (int j = 0; j < 4; ++j) acc[mt][nt][j] = 0.f;

    const int r8 = lane & 7;
    const int aRowIn = ((lane >> 3) & 1) * 8 + r8;
    const int aColB  = ((lane >> 4) & 1) * 16;
    const int bKrow  = lane & 15;
    const int bNcol  = w * 16 + ((lane >> 4) & 1) * 8;

    float4 xv[8], wv[2];
    const int xrow[8] = { (t) >> 5, (t + 256) >> 5, (t + 512) >> 5, (t + 768) >> 5,
                          (t + 1024) >> 5, (t + 1280) >> 5, (t + 1536) >> 5, (t + 1792) >> 5 };
    const int xqc  = t & 31;
    const int xhw  = hwt + xqc * 4;
    const bool xok = xhw < HW;          // HW%4==0 -> whole quad in range
    const int wrow[2] = { t >> 4, (t + 256) >> 4 };
    const int wqc  = t & 15;

#define ATT_LOAD(c0_)                                                         \
    do {                                                                      \
        _Pragma("unroll")                                                     \
        for (int i = 0; i < 8; ++i)                                           \
            xv[i] = xok ? *(const float4*)(X + (size_t)((c0_) + xrow[i]) * HW + xhw) \
                        : make_float4(0.f, 0.f, 0.f, 0.f);                    \
        _Pragma("unroll")                                                     \
        for (int i = 0; i < 2; ++i)                                           \
            wv[i] = *(const float4*)(attw + (size_t)wrow[i] * Cc + (c0_) + wqc * 4); \
    } while (0)

#define ATT_STORE(dst_)                                                       \
    do {                                                                      \
        char* db_ = (dst_);                                                   \
        _Pragma("unroll")                                                     \
        for (int i = 0; i < 8; ++i) {                                         \
            uint32_t h01, l01, h23, l23;                                      \
            split_pack(xv[i].x, xv[i].y, h01, l01);                           \
            split_pack(xv[i].z, xv[i].w, h23, l23);                           \
            uint32_t off = (uint32_t)(xrow[i] * PXB + xqc * 8);               \
            *(uint2*)(db_ + X_HI_OFF + off) = make_uint2(h01, h23);           \
            *(uint2*)(db_ + X_LO_OFF + off) = make_uint2(l01, l23);           \
        }                                                                     \
        _Pragma("unroll")                                                     \
        for (int i = 0; i < 2; ++i) {                                         \
            uint32_t h01, l01, h23, l23;                                      \
            split_pack(wv[i].x, wv[i].y, h01, l01);                           \
            split_pack(wv[i].z, wv[i].w, h23, l23);                           \
            uint32_t off = SWZ128((uint32_t)(wrow[i] * 128 + wqc * 8));       \
            *(uint2*)(db_ + W_HI_OFF + off) = make_uint2(h01, h23);           \
            *(uint2*)(db_ + W_LO_OFF + off) = make_uint2(l01, l23);           \
        }                                                                     \
    } while (0)

    ATT_LOAD(0);
    ATT_STORE(sbuf);
    __syncthreads();

    for (int ch = 0; ch < NKCH; ++ch) {
        const uint32_t abuf = abase + (uint32_t)(ch & 1) * ATT_BUF;
        if (ch + 1 < NKCH) ATT_LOAD((ch + 1) * KCH);   // LDG in flight over mma

#pragma unroll
        for (int ks = 0; ks < 4; ++ks) {
            uint32_t ah[2][4], al[2][4];
#pragma unroll
            for (int mt = 0; mt < 2; ++mt) {
                uint32_t aOff = SWZ128((uint32_t)((mt * 16 + aRowIn) * 128 +
                                                  ks * 32 + aColB));
                ldsm_x4(abuf + W_HI_OFF + aOff, ah[mt]);
                ldsm_x4(abuf + W_LO_OFF + aOff, al[mt]);
            }
            uint32_t bOff = (uint32_t)((ks * 16 + bKrow) * PXB + bNcol * 2);
            uint32_t bh[4], bl[4];
            ldsm_x4_t(abuf + X_HI_OFF + bOff, bh);
            ldsm_x4_t(abuf + X_LO_OFF + bOff, bl);
#pragma unroll
            for (int mt = 0; mt < 2; ++mt)
#pragma unroll
                for (int nt = 0; nt < 2; ++nt) {
                    mma_bf16(acc[mt][nt], ah[mt], bh[2 * nt], bh[2 * nt + 1]);
                    mma_bf16(acc[mt][nt], ah[mt], bl[2 * nt], bl[2 * nt + 1]);
                    mma_bf16(acc[mt][nt], al[mt], bh[2 * nt], bh[2 * nt + 1]);
                }
        }

        if (ch + 1 < NKCH) ATT_STORE(sbuf + ((ch + 1) & 1) * ATT_BUF);
        __syncthreads();
    }

    float* ob = out_att + (size_t)b * Mm * HW;
#pragma unroll
    for (int mt = 0; mt < 2; ++mt) {
        const int m  = mt * 16 + (lane >> 2);
        const float bs0 = __ldg(&attb[m]);
        const float bs8 = __ldg(&attb[m + 8]);
#pragma unroll
        for (int nt = 0; nt < 2; ++nt) {
            int hwc = hwt + w * 16 + nt * 8 + 2 * (lane & 3);
            if (hwc + 1 < HW) {
                ob[(size_t)m * HW + hwc]           = fmaxf(acc[mt][nt][0] + bs0, 0.f);
                ob[(size_t)m * HW + hwc + 1]       = fmaxf(acc[mt][nt][1] + bs0, 0.f);
                ob[(size_t)(m + 8) * HW + hwc]     = fmaxf(acc[mt][nt][2] + bs8, 0.f);
                ob[(size_t)(m + 8) * HW + hwc + 1] = fmaxf(acc[mt][nt][3] + bs8, 0.f);
            }
        }
    }
#undef ATT_LOAD
#undef ATT_STORE
}

// ---------------------------------------------------------------------------
// Kernel B (mma.sync, double-buffered): pool + fused sign-sqrt epilogue.
// D[128c x 32m] = (1/676) fm @ att^T; then f = sign(v)*sqrt(|v|+eps) written
// UNNORMALIZED to out_fm; block partial sum(f^2) atomicAdd'ed to g_ss[b].
// ---------------------------------------------------------------------------
#define CH       64
#define NCHUNK   11
#define A_HI_OFF 0
#define A_LO_OFF 16384
#define B_HI_OFF 32768
#define B_LO_OFF 36864
#define POOL_BUF 40960                  // 40*1024
#define POOL_SMEM_DYN (2 * POOL_BUF + 1024)

__global__ __launch_bounds__(256, 2) void k_pool_mma(
    const float* __restrict__ fmap, const float* __restrict__ att,
    float* __restrict__ out_fm)
{
    extern __shared__ char dyn_smem[];

    const int b  = blockIdx.y;
    const int c0 = blockIdx.x * 128;
    const int t  = threadIdx.x;
    const int w  = t >> 5, lane = t & 31;
    const int rw = w * 16;

    uint32_t raw = smem_u32(dyn_smem);
    uint32_t abase = (raw + 1023u) & ~1023u;
    char* sbuf = dyn_smem + (abase - raw);

    const float* Aruns = fmap + (size_t)(b * Cc + c0) * HW;
    const float* Bruns = att  + (size_t)b * Mm * HW;

    float acc[4][4];
#pragma unroll
    for (int p = 0; p < 4; ++p)
#pragma unroll
        for (int j = 0; j < 4; ++j) acc[p][j] = 0.f;

    const int r8   = lane & 7;
    const int aRow = rw + ((lane >> 3) & 1) * 8 + r8;
    const int aColM = ((lane >> 4) & 1) * 16;
    const int bRow0 = ((lane >> 4) & 1) * 8 + r8;
    const int bColM = ((lane >> 3) & 1) * 16;

    float4 av[8], bv[2];
    const int arow[8] = { (t) >> 4, (t + 256) >> 4, (t + 512) >> 4, (t + 768) >> 4,
                          (t + 1024) >> 4, (t + 1280) >> 4, (t + 1536) >> 4, (t + 1792) >> 4 };
    const int aqc = t & 15;

#define POOL_LOAD(hw0_)                                                       \
    do {                                                                      \
        const int hwq_ = (hw0_) + aqc * 4;                                    \
        const bool ok_ = hwq_ + 3 < HW;                                       \
        _Pragma("unroll")                                                     \
        for (int i = 0; i < 8; ++i)                                           \
            av[i] = ok_ ? *(const float4*)(Aruns + (size_t)arow[i] * HW + hwq_) \
                        : make_float4(0.f, 0.f, 0.f, 0.f);                    \
        _Pragma("unroll")                                                     \
        for (int i = 0; i < 2; ++i) {                                         \
            int row_ = (t + i * 256) >> 4;                                    \
            bv[i] = ok_ ? *(const float4*)(Bruns + (size_t)row_ * HW + hwq_)  \
                        : make_float4(0.f, 0.f, 0.f, 0.f);                    \
        }                                                                     \
    } while (0)

#define POOL_STORE(dst_)                                                      \
    do {                                                                      \
        char* db_ = (dst_);                                                   \
        _Pragma("unroll")                                                     \
        for (int i = 0; i < 8; ++i) {                                         \
            uint32_t h01, l01, h23, l23;                                      \
            split_pack(av[i].x, av[i].y, h01, l01);                           \
            split_pack(av[i].z, av[i].w, h23, l23);                           \
            uint32_t off = SWZ128((uint32_t)(arow[i] * 128 + aqc * 8));       \
            *(uint2*)(db_ + A_HI_OFF + off) = make_uint2(h01, h23);           \
            *(uint2*)(db_ + A_LO_OFF + off) = make_uint2(l01, l23);           \
        }                                                                     \
        _Pragma("unroll")                                                     \
        for (int i = 0; i < 2; ++i) {                                         \
            int row_ = (t + i * 256) >> 4;                                    \
            uint32_t h01, l01, h23, l23;                                      \
            split_pack(bv[i].x, bv[i].y, h01, l01);                           \
            split_pack(bv[i].z, bv[i].w, h23, l23);                           \
            uint32_t off = SWZ128((uint32_t)(row_ * 128 + aqc * 8));          \
            *(uint2*)(db_ + B_HI_OFF + off) = make_uint2(h01, h23);           \
            *(uint2*)(db_ + B_LO_OFF + off) = make_uint2(l01, l23);           \
        }                                                                     \
    } while (0)

    POOL_LOAD(0);
    POOL_STORE(sbuf);
    __syncthreads();

    for (int chunk = 0; chunk < NCHUNK; ++chunk) {
        const uint32_t abuf = abase + (uint32_t)(chunk & 1) * POOL_BUF;
        if (chunk + 1 < NCHUNK) POOL_LOAD((chunk + 1) * CH);

#pragma unroll
        for (int ks = 0; ks < 4; ++ks) {
            const uint32_t aOff = SWZ128((uint32_t)(aRow * 128 + ks * 32 + aColM));
            uint32_t ah[4], al[4];
            ldsm_x4(abuf + A_HI_OFF + aOff, ah);
            ldsm_x4(abuf + A_LO_OFF + aOff, al);
#pragma unroll
            for (int pp = 0; pp < 2; ++pp) {
                const uint32_t bOff =
                    SWZ128((uint32_t)((pp * 16 + bRow0) * 128 + ks * 32 + bColM));
                uint32_t bh[4], bl[4];
                ldsm_x4(abuf + B_HI_OFF + bOff, bh);   // NON-trans (K-major B)
                ldsm_x4(abuf + B_LO_OFF + bOff, bl);
                mma_bf16(acc[2 * pp],     ah, bh[0], bh[1]);
                mma_bf16(acc[2 * pp],     ah, bl[0], bl[1]);
                mma_bf16(acc[2 * pp],     al, bh[0], bh[1]);
                mma_bf16(acc[2 * pp + 1], ah, bh[2], bh[3]);
                mma_bf16(acc[2 * pp + 1], ah, bl[2], bl[3]);
                mma_bf16(acc[2 * pp + 1], al, bh[2], bh[3]);
            }
        }

        if (chunk + 1 < NCHUNK) POOL_STORE(sbuf + ((chunk + 1) & 1) * POOL_BUF);
        __syncthreads();
    }

    // ---- fused epilogue: sign-sqrt, write unnormalized f, reduce sum(f^2) ----
    const float inv = 1.f / (float)HW;
    const int crow = c0 + rw + (lane >> 2);
    float ssq = 0.f;
#pragma unroll
    for (int p = 0; p < 4; ++p) {
        const int n = p * 8 + (lane & 3) * 2;
#pragma unroll
        for (int j = 0; j < 4; ++j) {
            float x = acc[p][j] * inv;
            float f = (x == 0.f) ? 0.f : copysignf(sqrtf(fabsf(x) + 1e-12f), x);
            acc[p][j] = f;
            ssq += f * f;
        }
        out_fm[((size_t)b * Mm + n)     * Cc + crow]     = acc[p][0];
        out_fm[((size_t)b * Mm + n + 1) * Cc + crow]     = acc[p][1];
        out_fm[((size_t)b * Mm + n)     * Cc + crow + 8] = acc[p][2];
        out_fm[((size_t)b * Mm + n + 1) * Cc + crow + 8] = acc[p][3];
    }
    __shared__ float red[8];
#pragma unroll
    for (int o = 16; o; o >>= 1) ssq += __shfl_xor_sync(0xffffffffu, ssq, o);
    if (lane == 0) red[w] = ssq;
    __syncthreads();
    if (t < 8) {
        float s = red[t];
#pragma unroll
        for (int o = 4; o; o >>= 1) s += __shfl_xor_sync(0xffu, s, o);
        if (t == 0) atomicAdd(&g_ss[b], s);
    }
#undef POOL_LOAD
#undef POOL_STORE
}

// ---------------------------------------------------------------------------
// Kernel C: scales from g_ss; p initialized with bias.
// ---------------------------------------------------------------------------
__global__ __launch_bounds__(256) void k_scale(
    const float* __restrict__ fcb, float* __restrict__ out_p)
{
    if (blockIdx.x == 0 && threadIdx.x < Bn) {
        float s = 1.f / fmaxf(sqrtf(g_ss[threadIdx.x]), 1e-12f);
        g_scale[threadIdx.x] = s;
        g_scale100[threadIdx.x] = 100.f * s;
    }
    int i = blockIdx.x * 256 + threadIdx.x;
    if (i < Bn * NCLS) out_p[i] = __ldg(&fcb[i % NCLS]);
}

// ---------------------------------------------------------------------------
// Kernel D (mma.sync, double-buffered, split-k 96):
// p[b,n] += sum_k (f_unnorm[b,k] * g_scale100[b]) * fcw[n,k]
// Grid (96 ksplit, 4 ntiles of 64) = 384 CTAs (1.3 waves at 2 CTA/SM).
// Per CTA: D[64b x 64n], K = 256 in 4 chunks of 64.
// ---------------------------------------------------------------------------
#define FC_NSPLIT 96
#define FC_KS     (MC / FC_NSPLIT)      // 256
#define FC_NCH    (FC_KS / 64)          // 4
#define FA_HI 0
#define FA_LO 8192
#define FB_HI 16384
#define FB_LO 24576
#define FC_BUF 32768
#define FC_SMEM_DYN (2 * FC_BUF + 1024)

__global__ __launch_bounds__(256, 2) void k_fc_mma(
    const float* __restrict__ fmn, const float* __restrict__ fcw,
    float* __restrict__ out_p)
{
    extern __shared__ char dyn_smem[];
    const int k0 = blockIdx.x * FC_KS;
    const int n0 = blockIdx.y * 64;
    const int t  = threadIdx.x;
    const int w  = t >> 5, lane = t & 31;
    const int wm = w & 3, wn = w >> 2;

    uint32_t raw = smem_u32(dyn_smem);
    uint32_t abase = (raw + 1023u) & ~1023u;
    char* sbuf = dyn_smem + (abase - raw);

    float acc[4][4];
#pragma unroll
    for (int p = 0; p < 4; ++p)
#pragma unroll
        for (int j = 0; j < 4; ++j) acc[p][j] = 0.f;

    const int r8   = lane & 7;
    const int aRow = wm * 16 + ((lane >> 3) & 1) * 8 + r8;
    const int aColM = ((lane >> 4) & 1) * 16;
    const int bRow0 = wn * 32 + ((lane >> 4) & 1) * 8 + r8;
    const int bColM = ((lane >> 3) & 1) * 16;

    // staging coords
    const int srow = t >> 4, sqc = t & 15;        // +16 rows per i-step
    float4 avv[4], bvv[4];
    float sA[4];
#pragma unroll
    for (int i = 0; i < 4; ++i)
        sA[i] = g_scale100[(srow + i * 16) & 63];

#define FC_LOAD(kc_)                                                          \
    do {                                                                      \
        _Pragma("unroll")                                                     \
        for (int i = 0; i < 4; ++i) {                                         \
            int row = srow + i * 16;                                          \
            float4 v = *(const float4*)(fmn + (size_t)row * MC + (kc_) + sqc * 4); \
            v.x *= sA[i]; v.y *= sA[i]; v.z *= sA[i]; v.w *= sA[i];           \
            avv[i] = v;                                                       \
            int n = n0 + row;                                                 \
            bvv[i] = (n < NCLS)                                               \
                ? *(const float4*)(fcw + (size_t)n * MC + (kc_) + sqc * 4)    \
                : make_float4(0.f, 0.f, 0.f, 0.f);                            \
        }                                                                     \
    } while (0)

#define FC_STORE(dst_)                                                        \
    do {                                                                      \
        char* db_ = (dst_);                                                   \
        _Pragma("unroll")                                                     \
        for (int i = 0; i < 4; ++i) {                                         \
            int row = srow + i * 16;                                          \
            uint32_t off = SWZ128((uint32_t)(row * 128 + sqc * 8));           \
            uint32_t h01, l01, h23, l23;                                      \
            split_pack(avv[i].x, avv[i].y, h01, l01);                         \
            split_pack(avv[i].z, avv[i].w, h23, l23);                         \
            *(uint2*)(db_ + FA_HI + off) = make_uint2(h01, h23);              \
            *(uint2*)(db_ + FA_LO + off) = make_uint2(l01, l23);              \
            split_pack(bvv[i].x, bvv[i].y, h01, l01);                         \
            split_pack(bvv[i].z, bvv[i].w, h23, l23);                         \
            *(uint2*)(db_ + FB_HI + off) = make_uint2(h01, h23);              \
            *(uint2*)(db_ + FB_LO + off) = make_uint2(l01, l23);              \
        }                                                                     \
    } while (0)

    FC_LOAD(k0);
    FC_STORE(sbuf);
    __syncthreads();

    for (int ch = 0; ch < FC_NCH; ++ch) {
        const uint32_t abuf = abase + (uint32_t)(ch & 1) * FC_BUF;
        if (ch + 1 < FC_NCH) FC_LOAD(k0 + (ch + 1) * 64);

#pragma unroll
        for (int ks = 0; ks < 4; ++ks) {
            const uint32_t aOff = SWZ128((uint32_t)(aRow * 128 + ks * 32 + aColM));
            uint32_t ah[4], al[4];
            ldsm_x4(abuf + FA_HI + aOff, ah);
            ldsm_x4(abuf + FA_LO + aOff, al);
#pragma unroll
            for (int pp = 0; pp < 2; ++pp) {
                const uint32_t bOff =
                    SWZ128((uint32_t)((bRow0 + pp * 16) * 128 + ks * 32 + bColM));
                uint32_t bh[4], bl[4];
                ldsm_x4(abuf + FB_HI + bOff, bh);
                ldsm_x4(abuf + FB_LO + bOff, bl);
                mma_bf16(acc[2 * pp],     ah, bh[0], bh[1]);
                mma_bf16(acc[2 * pp],     ah, bl[0], bl[1]);
                mma_bf16(acc[2 * pp],     al, bh[0], bh[1]);
                mma_bf16(acc[2 * pp + 1], ah, bh[2], bh[3]);
                mma_bf16(acc[2 * pp + 1], ah, bl[2], bl[3]);
                mma_bf16(acc[2 * pp + 1], al, bh[2], bh[3]);
            }
        }

        if (ch + 1 < FC_NCH) FC_STORE(sbuf + ((ch + 1) & 1) * FC_BUF);
        __syncthreads();
    }

    // epilogue: p[b, n] += acc (scale folded into A staging; bias pre-written)
    const int brow = wm * 16 + (lane >> 2);
#pragma unroll
    for (int p = 0; p < 4; ++p) {
        const int n = n0 + wn * 32 + p * 8 + (lane & 3) * 2;
        if (n < NCLS) {
            atomicAdd(&out_p[brow * NCLS + n],       acc[p][0]);
            atomicAdd(&out_p[(brow + 8) * NCLS + n], acc[p][2]);
        }
        if (n + 1 < NCLS) {
            atomicAdd(&out_p[brow * NCLS + n + 1],       acc[p][1]);
            atomicAdd(&out_p[(brow + 8) * NCLS + n + 1], acc[p][3]);
        }
    }
#undef FC_LOAD
#undef FC_STORE
}

// ---------------------------------------------------------------------------
// Kernel E: normalize fm in place, float4-vectorized.
// grid (24, 64) x 256 thr: 24*256 quads = 24576 floats = MC exactly.
// ---------------------------------------------------------------------------
__global__ __launch_bounds__(256) void k_norm(float* __restrict__ out_fm)
{
    const int b = blockIdx.y;
    const float s = g_scale[b];
    float4* p = (float4*)(out_fm + (size_t)b * MC) + blockIdx.x * 256 + threadIdx.x;
    float4 v = *p;
    v.x *= s; v.y *= s; v.z *= s; v.w *= s;
    *p = v;
}

// ---------------------------------------------------------------------------
extern "C" void kernel_launch(void* const* d_in, const int* in_sizes, int n_in,
                              void* d_out, int out_size)
{
    const float* fmap = (const float*)d_in[0];
    const float* attw = (const float*)d_in[1];
    const float* attb = (const float*)d_in[2];
    const float* fcw  = (const float*)d_in[3];
    const float* fcb  = (const float*)d_in[4];
    float* out     = (float*)d_out;
    float* out_p   = out + OFF_P;
    float* out_fm  = out + OFF_FM;
    float* out_att = out + OFF_ATT;
    (void)in_sizes; (void)n_in; (void)out_size;

    // >48KB dynamic smem opt-in (attribute set, not an allocation; idempotent)
    cudaFuncSetAttribute(k_att_mma,  cudaFuncAttributeMaxDynamicSharedMemorySize,
                         ATT_SMEM_DYN);
    cudaFuncSetAttribute(k_pool_mma, cudaFuncAttributeMaxDynamicSharedMemorySize,
                         POOL_SMEM_DYN);
    cudaFuncSetAttribute(k_fc_mma,   cudaFuncAttributeMaxDynamicSharedMemorySize,
                         FC_SMEM_DYN);

    // 5 launches; ncu capture slot (idx 3) = k_fc_mma (verifying split-k 96).
    k_att_mma <<<dim3(6, 64), 256, ATT_SMEM_DYN>>>(fmap, attw, attb, out_att);
    k_pool_mma<<<dim3(6, 64), 256, POOL_SMEM_DYN>>>(fmap, out_att, out_fm);
    k_scale   <<<50, 256>>>(fcb, out_p);
    k_fc_mma  <<<dim3(FC_NSPLIT, 4), 256, FC_SMEM_DYN>>>(out_fm, fcw, out_p);
    k_norm    <<<dim3(24, 64), 256>>>(out_fm);
}